// round 1
// baseline (speedup 1.0000x reference)
#include <cuda_runtime.h>
#include <cuda_bf16.h>

#define DM 512
#define SN 64
#define NBATCH 4
#define SEQ 2048
#define M_TOT (NBATCH*SEQ)   // 8192

// ---------------- scratch (no runtime allocation allowed) ----------------
__device__ float g_u[M_TOT * DM];      // input-projected u  [b*t, d]
__device__ float g_gate[M_TOT * DM];   // sigmoid gate       [b*t, d]
__device__ float g_y[M_TOT * DM];      // SSM output + skip  [b*t, d]
__device__ float g_ar[DM * SN];
__device__ float g_ai[DM * SN];
__device__ float g_cb[DM * SN];

// ---------------- parameter precompute: Abar = exp(dt*A), cb = C*B*dt ----
__global__ void param_kernel(const float* __restrict__ log_A_real,
                             const float* __restrict__ A_imag,
                             const float* __restrict__ B_p,
                             const float* __restrict__ C_p,
                             const float* __restrict__ log_dt)
{
    int idx = blockIdx.x * blockDim.x + threadIdx.x;
    if (idx >= DM * SN) return;
    int d = idx / SN;
    float dt  = expf(log_dt[d]);
    float are = -expf(log_A_real[idx]);
    float aim = A_imag[idx];
    float r = expf(are * dt);
    float s, c;
    sincosf(aim * dt, &s, &c);
    g_ar[idx] = r * c;
    g_ai[idx] = r * s;
    g_cb[idx] = C_p[idx] * B_p[idx] * dt;
}

// ---------------- fp32 SIMT GEMM: C[M,N] = A[M,K] * B[N,K]^T -------------
// MODE 0: plain store
// MODE 1: store sigmoid(acc + bias[n])
// MODE 2: store xres + gate * acc
#define BM 128
#define BN 64
#define BK 16
#define TM 8
#define TN 4

template<int MODE>
__global__ __launch_bounds__(256, 2) void gemm_kernel(
    const float* __restrict__ A, const float* __restrict__ Bm,
    float* __restrict__ C,
    const float* __restrict__ bias,
    const float* __restrict__ xres, const float* __restrict__ gate,
    int M, int N, int K)
{
    __shared__ float As[BK][BM + 4];
    __shared__ float Bs[BK][BN + 4];

    const int tid = threadIdx.x;
    const int tx  = tid & 15;      // 0..15 -> N
    const int ty  = tid >> 4;      // 0..15 -> M
    const int m0  = blockIdx.y * BM;
    const int n0  = blockIdx.x * BN;

    // global-load mapping
    const int r0  = tid >> 2;           // 0..63
    const int akc = (tid & 3) * 4;      // 0,4,8,12

    const float* Ag0 = A  + (size_t)(m0 + r0)      * K + akc;
    const float* Ag1 = A  + (size_t)(m0 + r0 + 64) * K + akc;
    const float* Bg  = Bm + (size_t)(n0 + r0)      * K + akc;

    float4 a0 = *(const float4*)(Ag0);
    float4 a1 = *(const float4*)(Ag1);
    float4 b0 = *(const float4*)(Bg);

    float acc[TM][TN];
    #pragma unroll
    for (int i = 0; i < TM; i++)
        #pragma unroll
        for (int j = 0; j < TN; j++) acc[i][j] = 0.f;

    for (int kt = 0; kt < K; kt += BK) {
        // stage current tile to shared (transposed: [k][row])
        As[akc+0][r0]      = a0.x; As[akc+1][r0]      = a0.y;
        As[akc+2][r0]      = a0.z; As[akc+3][r0]      = a0.w;
        As[akc+0][r0+64]   = a1.x; As[akc+1][r0+64]   = a1.y;
        As[akc+2][r0+64]   = a1.z; As[akc+3][r0+64]   = a1.w;
        Bs[akc+0][r0]      = b0.x; Bs[akc+1][r0]      = b0.y;
        Bs[akc+2][r0]      = b0.z; Bs[akc+3][r0]      = b0.w;
        __syncthreads();

        // prefetch next tile
        if (kt + BK < K) {
            a0 = *(const float4*)(Ag0 + kt + BK);
            a1 = *(const float4*)(Ag1 + kt + BK);
            b0 = *(const float4*)(Bg  + kt + BK);
        }

        #pragma unroll
        for (int k = 0; k < BK; k++) {
            float4 av0 = *(const float4*)&As[k][ty * TM];
            float4 av1 = *(const float4*)&As[k][ty * TM + 4];
            float4 bv  = *(const float4*)&Bs[k][tx * TN];
            float a[TM] = {av0.x, av0.y, av0.z, av0.w, av1.x, av1.y, av1.z, av1.w};
            float b[TN] = {bv.x, bv.y, bv.z, bv.w};
            #pragma unroll
            for (int i = 0; i < TM; i++)
                #pragma unroll
                for (int j = 0; j < TN; j++)
                    acc[i][j] = fmaf(a[i], b[j], acc[i][j]);
        }
        __syncthreads();
    }

    const int col = n0 + tx * TN;
    #pragma unroll
    for (int i = 0; i < TM; i++) {
        const int row = m0 + ty * TM + i;
        const size_t off = (size_t)row * N + col;
        float4 v = make_float4(acc[i][0], acc[i][1], acc[i][2], acc[i][3]);
        if (MODE == 1) {
            v.x = 1.f / (1.f + __expf(-(v.x + bias[col + 0])));
            v.y = 1.f / (1.f + __expf(-(v.y + bias[col + 1])));
            v.z = 1.f / (1.f + __expf(-(v.z + bias[col + 2])));
            v.w = 1.f / (1.f + __expf(-(v.w + bias[col + 3])));
        } else if (MODE == 2) {
            float4 xv = *(const float4*)&xres[off];
            float4 gv = *(const float4*)&gate[off];
            v.x = xv.x + gv.x * v.x;
            v.y = xv.y + gv.y * v.y;
            v.z = xv.z + gv.z * v.z;
            v.w = xv.w + gv.w * v.w;
        }
        *(float4*)&C[off] = v;
    }
}

// ---------------- S4D diagonal scan --------------------------------------
// One warp per (b, d) sequence. 64 complex states -> 2 per lane.
// g' = Abar*g + cb*u  (cb real);  y[t] = sum_n Re(g_n) + D_p[d]*u[t]
// Cross-lane reduction deferred per 32-step tile via padded smem transpose.
__global__ __launch_bounds__(128) void scan_kernel(const float* __restrict__ D_p)
{
    __shared__ float sp[4][32 * 33];
    const int w    = threadIdx.x >> 5;
    const int lane = threadIdx.x & 31;
    const int d    = blockIdx.x * 4 + w;
    const int b    = blockIdx.y;
    float* spw = sp[w];

    const int base = d * SN;
    const float ar0 = g_ar[base + lane];
    const float ai0 = g_ai[base + lane];
    const float cb0 = g_cb[base + lane];
    const float ar1 = g_ar[base + 32 + lane];
    const float ai1 = g_ai[base + 32 + lane];
    const float cb1 = g_cb[base + 32 + lane];
    const float Dp  = D_p[d];

    const float* up = g_u + (size_t)(b * SEQ) * DM + d;
    float*       yp = g_y + (size_t)(b * SEQ) * DM + d;

    float gr0 = 0.f, gi0 = 0.f, gr1 = 0.f, gi1 = 0.f;
    float ucur = up[(size_t)lane * DM];

    const int NT = SEQ / 32;   // 64 tiles
    for (int tt = 0; tt < NT; tt++) {
        float unext = 0.f;
        if (tt + 1 < NT) unext = up[(size_t)((tt + 1) * 32 + lane) * DM];

        #pragma unroll
        for (int j = 0; j < 32; j++) {
            float uj = __shfl_sync(0xffffffffu, ucur, j);
            float n0r = fmaf(ar0, gr0, fmaf(-ai0, gi0, cb0 * uj));
            float n0i = fmaf(ai0, gr0, ar0 * gi0);
            float n1r = fmaf(ar1, gr1, fmaf(-ai1, gi1, cb1 * uj));
            float n1i = fmaf(ai1, gr1, ar1 * gi1);
            gr0 = n0r; gi0 = n0i; gr1 = n1r; gi1 = n1i;
            spw[j * 33 + lane] = n0r + n1r;   // partial for timestep j
        }
        __syncwarp();

        // lane L produces y[tt*32 + L]: sum partials over all 32 lanes
        float acc = Dp * ucur;                // ucur is u[tt*32 + lane]
        #pragma unroll
        for (int k2 = 0; k2 < 32; k2++) acc += spw[lane * 33 + k2];
        yp[(size_t)(tt * 32 + lane) * DM] = acc;
        __syncwarp();

        ucur = unext;
    }
}

// ---------------- launch --------------------------------------------------
extern "C" void kernel_launch(void* const* d_in, const int* in_sizes, int n_in,
                              void* d_out, int out_size)
{
    const float* x          = (const float*)d_in[0];
    const float* log_A_real = (const float*)d_in[1];
    const float* A_imag     = (const float*)d_in[2];
    const float* B_p        = (const float*)d_in[3];
    const float* C_p        = (const float*)d_in[4];
    const float* D_p        = (const float*)d_in[5];
    const float* log_dt     = (const float*)d_in[6];
    const float* W_in       = (const float*)d_in[7];
    const float* W_out      = (const float*)d_in[8];
    const float* W_gate     = (const float*)d_in[9];
    const float* b_gate     = (const float*)d_in[10];
    float* out = (float*)d_out;

    float *pu, *pg, *py;
    cudaGetSymbolAddress((void**)&pu, g_u);
    cudaGetSymbolAddress((void**)&pg, g_gate);
    cudaGetSymbolAddress((void**)&py, g_y);

    param_kernel<<<(DM * SN + 255) / 256, 256>>>(log_A_real, A_imag, B_p, C_p, log_dt);

    dim3 gg(DM / BN, M_TOT / BM);   // (8, 64)
    gemm_kernel<0><<<gg, 256>>>(x,  W_in,   pu,  nullptr, nullptr, nullptr, M_TOT, DM, DM);
    gemm_kernel<1><<<gg, 256>>>(x,  W_gate, pg,  b_gate,  nullptr, nullptr, M_TOT, DM, DM);

    scan_kernel<<<dim3(DM / 4, NBATCH), 128>>>(D_p);

    gemm_kernel<2><<<gg, 256>>>(py, W_out,  out, nullptr, x,       pg,      M_TOT, DM, DM);
}

// round 3
// speedup vs baseline: 1.1933x; 1.1933x over previous
#include <cuda_runtime.h>
#include <cuda_bf16.h>
#include <cstdint>

#define DM 512
#define SN 64
#define NBATCH 4
#define SEQ 2048
#define M_TOT (NBATCH*SEQ)   // 8192
#define KDIM 512

// ---------------- scratch (no runtime allocation allowed) ----------------
__device__ float g_u[M_TOT * DM];        // input-projected u  (fp32, scan input)
__device__ float g_gate[M_TOT * DM];     // sigmoid gate (fp32)
__device__ __nv_bfloat16 g_xh[M_TOT * DM];
__device__ __nv_bfloat16 g_xl[M_TOT * DM];
__device__ __nv_bfloat16 g_yh[M_TOT * DM];
__device__ __nv_bfloat16 g_yl[M_TOT * DM];
__device__ __nv_bfloat16 g_wih[DM * DM], g_wil[DM * DM];
__device__ __nv_bfloat16 g_wgh[DM * DM], g_wgl[DM * DM];
__device__ __nv_bfloat16 g_woh[DM * DM], g_wol[DM * DM];
__device__ float g_ar[DM * SN];
__device__ float g_ai[DM * SN];
__device__ float g_cb[DM * SN];

// ---------------- f32x2 packed helpers (sm_100+) --------------------------
__device__ __forceinline__ unsigned long long pk2(float a, float b) {
    unsigned long long r;
    asm("mov.b64 %0, {%1, %2};" : "=l"(r) : "f"(a), "f"(b));
    return r;
}
__device__ __forceinline__ void upk2(unsigned long long v, float& a, float& b) {
    asm("mov.b64 {%0, %1}, %2;" : "=f"(a), "=f"(b) : "l"(v));
}
__device__ __forceinline__ unsigned long long fma2(unsigned long long a,
                                                   unsigned long long b,
                                                   unsigned long long c) {
    unsigned long long r;
    asm("fma.rn.f32x2 %0, %1, %2, %3;" : "=l"(r) : "l"(a), "l"(b), "l"(c));
    return r;
}
__device__ __forceinline__ unsigned long long mul2(unsigned long long a,
                                                   unsigned long long b) {
    unsigned long long r;
    asm("mul.rn.f32x2 %0, %1, %2;" : "=l"(r) : "l"(a), "l"(b));
    return r;
}
__device__ __forceinline__ unsigned long long add2(unsigned long long a,
                                                   unsigned long long b) {
    unsigned long long r;
    asm("add.rn.f32x2 %0, %1, %2;" : "=l"(r) : "l"(a), "l"(b));
    return r;
}

// ---------------- parameter precompute -----------------------------------
__global__ void param_kernel(const float* __restrict__ log_A_real,
                             const float* __restrict__ A_imag,
                             const float* __restrict__ B_p,
                             const float* __restrict__ C_p,
                             const float* __restrict__ log_dt)
{
    int idx = blockIdx.x * blockDim.x + threadIdx.x;
    if (idx >= DM * SN) return;
    int d = idx / SN;
    float dt  = expf(log_dt[d]);
    float are = -expf(log_A_real[idx]);
    float aim = A_imag[idx];
    float r = expf(are * dt);
    float s, c;
    sincosf(aim * dt, &s, &c);
    g_ar[idx] = r * c;
    g_ai[idx] = r * s;
    g_cb[idx] = C_p[idx] * B_p[idx] * dt;
}

// ---------------- fp32 -> bf16 hi/lo split --------------------------------
__global__ void split_kernel(const float* __restrict__ in,
                             __nv_bfloat16* __restrict__ hi,
                             __nv_bfloat16* __restrict__ lo, int n)
{
    int i = blockIdx.x * blockDim.x + threadIdx.x;
    if (i >= n) return;
    float v = in[i];
    __nv_bfloat16 h = __float2bfloat16(v);
    hi[i] = h;
    lo[i] = __float2bfloat16(v - __bfloat162float(h));
}

// ---------------- bf16x3 tensor-core GEMM ---------------------------------
// C[M,N] = A[M,K] * B[N,K]^T, where A ~ Ah+Al, B ~ Bh+Bl (bf16 splits).
// acc = Ah*Bh + Ah*Bl + Al*Bh   (fp32 accumulate, err ~2^-16)
// MODE 0: plain fp32 store
// MODE 1: store sigmoid(acc + bias[n])
// MODE 2: store xres + gate * acc
#define GBM 128
#define GBN 64
#define GBK 32
#define RSTRIDE 40                 // padded row stride in bf16 elems (80B)
#define A_ELEMS (GBM * RSTRIDE)    // 5120
#define B_ELEMS (GBN * RSTRIDE)    // 2560
#define STAGE_ELEMS (2*A_ELEMS + 2*B_ELEMS)  // 15360 bf16
#define NSTAGES 3
#define GEMM_SMEM (NSTAGES * STAGE_ELEMS * 2) // 92160 bytes

__device__ __forceinline__ void ldm_x4(uint32_t& r0, uint32_t& r1,
                                       uint32_t& r2, uint32_t& r3, uint32_t addr)
{
    asm volatile("ldmatrix.sync.aligned.m8n8.x4.shared.b16 {%0,%1,%2,%3}, [%4];"
                 : "=r"(r0), "=r"(r1), "=r"(r2), "=r"(r3) : "r"(addr));
}

__device__ __forceinline__ void mma16816(float* c, const uint32_t* a,
                                         uint32_t b0, uint32_t b1)
{
    asm volatile(
        "mma.sync.aligned.m16n8k16.row.col.f32.bf16.bf16.f32 "
        "{%0,%1,%2,%3}, {%4,%5,%6,%7}, {%8,%9}, {%0,%1,%2,%3};"
        : "+f"(c[0]), "+f"(c[1]), "+f"(c[2]), "+f"(c[3])
        : "r"(a[0]), "r"(a[1]), "r"(a[2]), "r"(a[3]), "r"(b0), "r"(b1));
}

#define CP16(dst, src) \
    asm volatile("cp.async.cg.shared.global [%0], [%1], 16;" :: "r"(dst), "l"(src))
#define CP_COMMIT() asm volatile("cp.async.commit_group;")
#define CP_WAIT1()  asm volatile("cp.async.wait_group 1;")

template<int MODE>
__global__ __launch_bounds__(256) void gemm_bf16x3_kernel(
    const __nv_bfloat16* __restrict__ Ah, const __nv_bfloat16* __restrict__ Al,
    const __nv_bfloat16* __restrict__ Bh, const __nv_bfloat16* __restrict__ Bl,
    float* __restrict__ C,
    const float* __restrict__ bias,
    const float* __restrict__ xres, const float* __restrict__ gate)
{
    extern __shared__ __nv_bfloat16 smem[];
    const uint32_t sbase = (uint32_t)__cvta_generic_to_shared(smem);

    const int tid  = threadIdx.x;
    const int lane = tid & 31;
    const int warp = tid >> 5;
    const int wm   = warp & 3;        // 0..3 -> m
    const int wn   = warp >> 2;       // 0..1 -> n
    const int m0   = blockIdx.y * GBM;
    const int n0   = blockIdx.x * GBN;

    // cp.async source mapping
    const int arow = tid >> 2;        // 0..63
    const int ac   = (tid & 3) * 8;   // bf16 element offset of 16B chunk

    const __nv_bfloat16* gAh0 = Ah + (size_t)(m0 + arow)      * KDIM + ac;
    const __nv_bfloat16* gAh1 = Ah + (size_t)(m0 + arow + 64) * KDIM + ac;
    const __nv_bfloat16* gAl0 = Al + (size_t)(m0 + arow)      * KDIM + ac;
    const __nv_bfloat16* gAl1 = Al + (size_t)(m0 + arow + 64) * KDIM + ac;
    const __nv_bfloat16* gBh  = Bh + (size_t)(n0 + arow)      * KDIM + ac;
    const __nv_bfloat16* gBl  = Bl + (size_t)(n0 + arow)      * KDIM + ac;

    // smem dest offsets (bytes), per stage added later
    const uint32_t dA0 = (uint32_t)((arow       * RSTRIDE + ac) * 2);
    const uint32_t dA1 = (uint32_t)(((arow + 64) * RSTRIDE + ac) * 2);
    const uint32_t dB  = (uint32_t)((arow       * RSTRIDE + ac) * 2);

    auto load_stage = [&](int s, int kk) {
        uint32_t sb = sbase + (uint32_t)(s * STAGE_ELEMS * 2);
        uint32_t aH = sb;
        uint32_t aL = sb + A_ELEMS * 2;
        uint32_t bH = sb + 2 * A_ELEMS * 2;
        uint32_t bL = sb + (2 * A_ELEMS + B_ELEMS) * 2;
        CP16(aH + dA0, gAh0 + kk);
        CP16(aH + dA1, gAh1 + kk);
        CP16(aL + dA0, gAl0 + kk);
        CP16(aL + dA1, gAl1 + kk);
        CP16(bH + dB,  gBh  + kk);
        CP16(bL + dB,  gBl  + kk);
    };

    float acc[2][4][4];
    #pragma unroll
    for (int i = 0; i < 2; i++)
        #pragma unroll
        for (int j = 0; j < 4; j++)
            #pragma unroll
            for (int k = 0; k < 4; k++) acc[i][j][k] = 0.f;

    load_stage(0, 0);  CP_COMMIT();
    load_stage(1, GBK); CP_COMMIT();

    // ldmatrix per-lane addressing
    const int grp = lane >> 3;             // 0..3
    const int rin = lane & 7;
    const int rowsel = (grp & 1) * 8 + rin;
    const int colsel = (grp >> 1) * 8;     // bf16 elems

    const int NKC = KDIM / GBK;            // 16
    for (int kc = 0; kc < NKC; kc++) {
        CP_WAIT1();
        __syncthreads();
        if (kc + 2 < NKC) load_stage((kc + 2) % NSTAGES, (kc + 2) * GBK);
        CP_COMMIT();

        const int s = kc % NSTAGES;
        const uint32_t sb = sbase + (uint32_t)(s * STAGE_ELEMS * 2);
        const uint32_t aH = sb;
        const uint32_t aL = sb + A_ELEMS * 2;
        const uint32_t bH = sb + 2 * A_ELEMS * 2;
        const uint32_t bL = sb + (2 * A_ELEMS + B_ELEMS) * 2;

        #pragma unroll
        for (int ks = 0; ks < 2; ks++) {
            const int kb = ks * 16 + colsel;
            uint32_t ah[2][4], al[2][4], bh[2][4], bl[2][4];
            #pragma unroll
            for (int mt = 0; mt < 2; mt++) {
                uint32_t off = (uint32_t)(((wm * 32 + mt * 16 + rowsel) * RSTRIDE + kb) * 2);
                ldm_x4(ah[mt][0], ah[mt][1], ah[mt][2], ah[mt][3], aH + off);
                ldm_x4(al[mt][0], al[mt][1], al[mt][2], al[mt][3], aL + off);
            }
            #pragma unroll
            for (int p = 0; p < 2; p++) {
                uint32_t off = (uint32_t)(((wn * 32 + p * 16 + rowsel) * RSTRIDE + kb) * 2);
                ldm_x4(bh[p][0], bh[p][1], bh[p][2], bh[p][3], bH + off);
                ldm_x4(bl[p][0], bl[p][1], bl[p][2], bl[p][3], bL + off);
            }
            #pragma unroll
            for (int mt = 0; mt < 2; mt++) {
                #pragma unroll
                for (int nt = 0; nt < 4; nt++) {
                    const int p = nt >> 1, o = nt & 1;
                    mma16816(acc[mt][nt], ah[mt], bh[p][0 + o], bh[p][2 + o]);
                    mma16816(acc[mt][nt], ah[mt], bl[p][0 + o], bl[p][2 + o]);
                    mma16816(acc[mt][nt], al[mt], bh[p][0 + o], bh[p][2 + o]);
                }
            }
        }
        __syncthreads();
    }

    // ------------- epilogue -------------
    const int r  = lane >> 2;
    const int cp = (lane & 3) * 2;
    #pragma unroll
    for (int mt = 0; mt < 2; mt++) {
        #pragma unroll
        for (int nt = 0; nt < 4; nt++) {
            const int col  = n0 + wn * 32 + nt * 8 + cp;
            const int row0 = m0 + wm * 32 + mt * 16 + r;
            #pragma unroll
            for (int h = 0; h < 2; h++) {
                const int row = row0 + h * 8;
                const size_t off = (size_t)row * DM + col;
                float v0 = acc[mt][nt][2 * h + 0];
                float v1 = acc[mt][nt][2 * h + 1];
                if (MODE == 1) {
                    v0 = 1.f / (1.f + __expf(-(v0 + bias[col + 0])));
                    v1 = 1.f / (1.f + __expf(-(v1 + bias[col + 1])));
                } else if (MODE == 2) {
                    float2 xv = *(const float2*)&xres[off];
                    float2 gv = *(const float2*)&gate[off];
                    v0 = xv.x + gv.x * v0;
                    v1 = xv.y + gv.y * v1;
                }
                float2 o = make_float2(v0, v1);
                *(float2*)&C[off] = o;
            }
        }
    }
}

// ---------------- S4D diagonal scan (packed f32x2) ------------------------
// One warp per (b, d) sequence. 64 complex states -> 2 per lane, packed into
// f32x2 pairs (state0, state1). Per step:
//   gr' = ar*gr - ai*gi + cb*u ;  gi' = ai*gr + ar*gi   (packed, FFMA2)
// Partial sums deferred per 32-step tile via padded smem transpose (64-bit).
__global__ __launch_bounds__(128) void scan_kernel(const float* __restrict__ D_p)
{
    __shared__ unsigned long long sp[4][32 * 33];
    const int w    = threadIdx.x >> 5;
    const int lane = threadIdx.x & 31;
    const int d    = blockIdx.x * 4 + w;
    const int b    = blockIdx.y;
    unsigned long long* spw = sp[w];

    const int base = d * SN;
    const unsigned long long ar2  = pk2(g_ar[base + lane],  g_ar[base + 32 + lane]);
    const unsigned long long ai2  = pk2(g_ai[base + lane],  g_ai[base + 32 + lane]);
    const unsigned long long nai2 = pk2(-g_ai[base + lane], -g_ai[base + 32 + lane]);
    const unsigned long long cb2  = pk2(g_cb[base + lane],  g_cb[base + 32 + lane]);
    const float Dp  = D_p[d];

    const float* up = g_u + (size_t)(b * SEQ) * DM + d;
    __nv_bfloat16* yh = g_yh + (size_t)(b * SEQ) * DM + d;
    __nv_bfloat16* yl = g_yl + (size_t)(b * SEQ) * DM + d;

    unsigned long long gr2 = 0ull, gi2 = 0ull;
    float ucur = up[(size_t)lane * DM];

    const int NT = SEQ / 32;   // 64 tiles
    for (int tt = 0; tt < NT; tt++) {
        float unext = 0.f;
        if (tt + 1 < NT) unext = up[(size_t)((tt + 1) * 32 + lane) * DM];

        #pragma unroll
        for (int j = 0; j < 32; j++) {
            float uj = __shfl_sync(0xffffffffu, ucur, j);
            unsigned long long u2  = pk2(uj, uj);
            unsigned long long nr  = fma2(ar2, gr2, fma2(nai2, gi2, mul2(cb2, u2)));
            unsigned long long ni  = fma2(ai2, gr2, mul2(ar2, gi2));
            gr2 = nr; gi2 = ni;
            spw[j * 33 + lane] = nr;   // packed partials for timestep j
        }
        __syncwarp();

        // lane L produces y[tt*32 + L]: sum packed partials over 32 lanes
        unsigned long long accA = spw[lane * 33 + 0];
        unsigned long long accB = spw[lane * 33 + 1];
        #pragma unroll
        for (int k2 = 2; k2 < 32; k2 += 2) {
            accA = add2(accA, spw[lane * 33 + k2]);
            accB = add2(accB, spw[lane * 33 + k2 + 1]);
        }
        accA = add2(accA, accB);
        float s0, s1;
        upk2(accA, s0, s1);
        float acc = fmaf(Dp, ucur, s0 + s1);

        const size_t oidx = (size_t)(tt * 32 + lane) * DM;
        __nv_bfloat16 h = __float2bfloat16(acc);
        yh[oidx] = h;
        yl[oidx] = __float2bfloat16(acc - __bfloat162float(h));
        __syncwarp();

        ucur = unext;
    }
}

// ---------------- launch --------------------------------------------------
extern "C" void kernel_launch(void* const* d_in, const int* in_sizes, int n_in,
                              void* d_out, int out_size)
{
    const float* x          = (const float*)d_in[0];
    const float* log_A_real = (const float*)d_in[1];
    const float* A_imag     = (const float*)d_in[2];
    const float* B_p        = (const float*)d_in[3];
    const float* C_p        = (const float*)d_in[4];
    const float* D_p        = (const float*)d_in[5];
    const float* log_dt     = (const float*)d_in[6];
    const float* W_in       = (const float*)d_in[7];
    const float* W_out      = (const float*)d_in[8];
    const float* W_gate     = (const float*)d_in[9];
    const float* b_gate     = (const float*)d_in[10];
    float* out = (float*)d_out;

    float *pu, *pg;
    __nv_bfloat16 *xh, *xl, *yh, *yl, *wih, *wil, *wgh, *wgl, *woh, *wol;
    cudaGetSymbolAddress((void**)&pu,  g_u);
    cudaGetSymbolAddress((void**)&pg,  g_gate);
    cudaGetSymbolAddress((void**)&xh,  g_xh);
    cudaGetSymbolAddress((void**)&xl,  g_xl);
    cudaGetSymbolAddress((void**)&yh,  g_yh);
    cudaGetSymbolAddress((void**)&yl,  g_yl);
    cudaGetSymbolAddress((void**)&wih, g_wih);
    cudaGetSymbolAddress((void**)&wil, g_wil);
    cudaGetSymbolAddress((void**)&wgh, g_wgh);
    cudaGetSymbolAddress((void**)&wgl, g_wgl);
    cudaGetSymbolAddress((void**)&woh, g_woh);
    cudaGetSymbolAddress((void**)&wol, g_wol);

    cudaFuncSetAttribute(gemm_bf16x3_kernel<0>,
                         cudaFuncAttributeMaxDynamicSharedMemorySize, GEMM_SMEM);
    cudaFuncSetAttribute(gemm_bf16x3_kernel<1>,
                         cudaFuncAttributeMaxDynamicSharedMemorySize, GEMM_SMEM);
    cudaFuncSetAttribute(gemm_bf16x3_kernel<2>,
                         cudaFuncAttributeMaxDynamicSharedMemorySize, GEMM_SMEM);

    param_kernel<<<(DM * SN + 255) / 256, 256>>>(log_A_real, A_imag, B_p, C_p, log_dt);

    split_kernel<<<(M_TOT * DM + 255) / 256, 256>>>(x, xh, xl, M_TOT * DM);
    split_kernel<<<(DM * DM + 255) / 256, 256>>>(W_in,   wih, wil, DM * DM);
    split_kernel<<<(DM * DM + 255) / 256, 256>>>(W_gate, wgh, wgl, DM * DM);
    split_kernel<<<(DM * DM + 255) / 256, 256>>>(W_out,  woh, wol, DM * DM);

    dim3 gg(DM / GBN, M_TOT / GBM);   // (8, 64)
    gemm_bf16x3_kernel<0><<<gg, 256, GEMM_SMEM>>>(xh, xl, wih, wil, pu,
                                                  nullptr, nullptr, nullptr);
    gemm_bf16x3_kernel<1><<<gg, 256, GEMM_SMEM>>>(xh, xl, wgh, wgl, pg,
                                                  b_gate, nullptr, nullptr);

    scan_kernel<<<dim3(DM / 4, NBATCH), 128>>>(D_p);

    gemm_bf16x3_kernel<2><<<gg, 256, GEMM_SMEM>>>(yh, yl, woh, wol, out,
                                                  nullptr, x, pg);
}

// round 5
// speedup vs baseline: 1.2900x; 1.0811x over previous
#include <cuda_runtime.h>
#include <cuda_bf16.h>
#include <cstdint>

#define DM 512
#define SN 64
#define NBATCH 4
#define SEQ 2048
#define M_TOT (NBATCH*SEQ)   // 8192
#define KDIM 512

// ---------------- scratch (no runtime allocation allowed) ----------------
__device__ float g_u[M_TOT * DM];
__device__ float g_gate[M_TOT * DM];
__device__ __nv_bfloat16 g_xh[M_TOT * DM];
__device__ __nv_bfloat16 g_xl[M_TOT * DM];
__device__ __nv_bfloat16 g_yh[M_TOT * DM];
__device__ __nv_bfloat16 g_yl[M_TOT * DM];
__device__ __nv_bfloat16 g_wih[DM * DM], g_wil[DM * DM];
__device__ __nv_bfloat16 g_wgh[DM * DM], g_wgl[DM * DM];
__device__ __nv_bfloat16 g_woh[DM * DM], g_wol[DM * DM];
__device__ float g_ar[DM * SN];
__device__ float g_ai[DM * SN];
__device__ float g_cb[DM * SN];

// ---------------- f32x2 packed helpers ------------------------------------
__device__ __forceinline__ unsigned long long pk2(float a, float b) {
    unsigned long long r;
    asm("mov.b64 %0, {%1, %2};" : "=l"(r) : "f"(a), "f"(b));
    return r;
}
__device__ __forceinline__ void upk2(unsigned long long v, float& a, float& b) {
    asm("mov.b64 {%0, %1}, %2;" : "=f"(a), "=f"(b) : "l"(v));
}
__device__ __forceinline__ unsigned long long fma2(unsigned long long a,
                                                   unsigned long long b,
                                                   unsigned long long c) {
    unsigned long long r;
    asm("fma.rn.f32x2 %0, %1, %2, %3;" : "=l"(r) : "l"(a), "l"(b), "l"(c));
    return r;
}
__device__ __forceinline__ unsigned long long mul2(unsigned long long a,
                                                   unsigned long long b) {
    unsigned long long r;
    asm("mul.rn.f32x2 %0, %1, %2;" : "=l"(r) : "l"(a), "l"(b));
    return r;
}
__device__ __forceinline__ unsigned long long add2(unsigned long long a,
                                                   unsigned long long b) {
    unsigned long long r;
    asm("add.rn.f32x2 %0, %1, %2;" : "=l"(r) : "l"(a), "l"(b));
    return r;
}

// ---------------- parameter precompute -----------------------------------
__global__ void param_kernel(const float* __restrict__ log_A_real,
                             const float* __restrict__ A_imag,
                             const float* __restrict__ B_p,
                             const float* __restrict__ C_p,
                             const float* __restrict__ log_dt)
{
    int idx = blockIdx.x * blockDim.x + threadIdx.x;
    if (idx >= DM * SN) return;
    int d = idx / SN;
    float dt  = expf(log_dt[d]);
    float are = -expf(log_A_real[idx]);
    float aim = A_imag[idx];
    float r = expf(are * dt);
    float s, c;
    sincosf(aim * dt, &s, &c);
    g_ar[idx] = r * c;
    g_ai[idx] = r * s;
    g_cb[idx] = C_p[idx] * B_p[idx] * dt;
}

// ---------------- fp32 -> bf16 hi/lo splits --------------------------------
__global__ void split_kernel(const float* __restrict__ in,
                             __nv_bfloat16* __restrict__ hi,
                             __nv_bfloat16* __restrict__ lo, int n)
{
    int i = blockIdx.x * blockDim.x + threadIdx.x;
    if (i >= n) return;
    float v = in[i];
    __nv_bfloat16 h = __float2bfloat16(v);
    hi[i] = h;
    lo[i] = __float2bfloat16(v - __bfloat162float(h));
}

__global__ void split3_kernel(const float* __restrict__ w0, const float* __restrict__ w1,
                              const float* __restrict__ w2,
                              __nv_bfloat16* __restrict__ h0, __nv_bfloat16* __restrict__ l0,
                              __nv_bfloat16* __restrict__ h1, __nv_bfloat16* __restrict__ l1,
                              __nv_bfloat16* __restrict__ h2, __nv_bfloat16* __restrict__ l2)
{
    int i = blockIdx.x * blockDim.x + threadIdx.x;
    if (i >= 3 * DM * DM) return;
    int which = i / (DM * DM);
    int j = i - which * (DM * DM);
    const float* src = (which == 0) ? w0 : (which == 1) ? w1 : w2;
    __nv_bfloat16* hh = (which == 0) ? h0 : (which == 1) ? h1 : h2;
    __nv_bfloat16* ll = (which == 0) ? l0 : (which == 1) ? l1 : l2;
    float v = src[j];
    __nv_bfloat16 h = __float2bfloat16(v);
    hh[j] = h;
    ll[j] = __float2bfloat16(v - __bfloat162float(h));
}

// ============================================================================
// bf16x3 mma.sync GEMM:  C[M,N] = A[M,K] * B[N,K]^T  (A~Ah+Al, B~Bh+Bl)
// Tile 256(M) x 128(N), 512 threads (16 warps, 4x4), warp tile 64x32.
// MODE 0: plain ; MODE 1: sigmoid(acc+bias) ; MODE 2: x + gate*acc
// ============================================================================
#define GBM 256
#define GBN 128
#define GBK 32
#define RSTRIDE 40                      // bf16 elems per row (80B, conflict-free)
#define A_ELEMS (GBM * RSTRIDE)         // 10240 per split
#define B_ELEMS (GBN * RSTRIDE)         // 5120 per split
#define STAGE_ELEMS (2*A_ELEMS + 2*B_ELEMS)   // 30720
#define NSTAGES 3
#define GEMM_SMEM (NSTAGES * STAGE_ELEMS * 2) // 184320 B

__device__ __forceinline__ void ldm_x4(uint32_t& r0, uint32_t& r1,
                                       uint32_t& r2, uint32_t& r3, uint32_t addr)
{
    asm volatile("ldmatrix.sync.aligned.m8n8.x4.shared.b16 {%0,%1,%2,%3}, [%4];"
                 : "=r"(r0), "=r"(r1), "=r"(r2), "=r"(r3) : "r"(addr));
}

__device__ __forceinline__ void mma16816(float* c, const uint32_t* a,
                                         uint32_t b0, uint32_t b1)
{
    asm volatile(
        "mma.sync.aligned.m16n8k16.row.col.f32.bf16.bf16.f32 "
        "{%0,%1,%2,%3}, {%4,%5,%6,%7}, {%8,%9}, {%0,%1,%2,%3};"
        : "+f"(c[0]), "+f"(c[1]), "+f"(c[2]), "+f"(c[3])
        : "r"(a[0]), "r"(a[1]), "r"(a[2]), "r"(a[3]), "r"(b0), "r"(b1));
}

#define CP16(dst, src) \
    asm volatile("cp.async.cg.shared.global [%0], [%1], 16;" :: "r"(dst), "l"(src))
#define CP_COMMIT() asm volatile("cp.async.commit_group;")
#define CP_WAIT1()  asm volatile("cp.async.wait_group 1;")

template<int MODE>
__global__ __launch_bounds__(512, 1) void gemm_bf16x3_kernel(
    const __nv_bfloat16* __restrict__ Ah, const __nv_bfloat16* __restrict__ Al,
    const __nv_bfloat16* __restrict__ Bh, const __nv_bfloat16* __restrict__ Bl,
    float* __restrict__ C,
    const float* __restrict__ bias,
    const float* __restrict__ xres, const float* __restrict__ gate)
{
    extern __shared__ __nv_bfloat16 smem[];
    const uint32_t sbase = (uint32_t)__cvta_generic_to_shared(smem);

    const int tid  = threadIdx.x;
    const int lane = tid & 31;
    const int warp = tid >> 5;
    const int wm   = warp & 3;        // 0..3 -> 64-row block
    const int wn   = warp >> 2;       // 0..3 -> 32-col block
    const int m0   = blockIdx.y * GBM;
    const int n0   = blockIdx.x * GBN;

    // cp.async mapping: 512 threads, each 6 16B chunks
    const int arow = tid >> 2;        // 0..127
    const int ac   = (tid & 3) * 8;   // 0,8,16,24 (bf16 elems)

    const __nv_bfloat16* gAh0 = Ah + (size_t)(m0 + arow)       * KDIM + ac;
    const __nv_bfloat16* gAh1 = Ah + (size_t)(m0 + arow + 128) * KDIM + ac;
    const __nv_bfloat16* gAl0 = Al + (size_t)(m0 + arow)       * KDIM + ac;
    const __nv_bfloat16* gAl1 = Al + (size_t)(m0 + arow + 128) * KDIM + ac;
    const __nv_bfloat16* gBh  = Bh + (size_t)(n0 + arow)       * KDIM + ac;
    const __nv_bfloat16* gBl  = Bl + (size_t)(n0 + arow)       * KDIM + ac;

    const uint32_t dA0 = (uint32_t)((arow        * RSTRIDE + ac) * 2);
    const uint32_t dA1 = (uint32_t)(((arow + 128) * RSTRIDE + ac) * 2);
    const uint32_t dB  = (uint32_t)((arow        * RSTRIDE + ac) * 2);

    auto load_stage = [&](int s, int kk) {
        uint32_t sb = sbase + (uint32_t)(s * STAGE_ELEMS * 2);
        uint32_t aH = sb;
        uint32_t aL = sb + A_ELEMS * 2;
        uint32_t bH = sb + 2 * A_ELEMS * 2;
        uint32_t bL = sb + (2 * A_ELEMS + B_ELEMS) * 2;
        CP16(aH + dA0, gAh0 + kk);
        CP16(aH + dA1, gAh1 + kk);
        CP16(aL + dA0, gAl0 + kk);
        CP16(aL + dA1, gAl1 + kk);
        CP16(bH + dB,  gBh  + kk);
        CP16(bL + dB,  gBl  + kk);
    };

    float acc[4][4][4];   // [mt][nt][quad]
    #pragma unroll
    for (int i = 0; i < 4; i++)
        #pragma unroll
        for (int j = 0; j < 4; j++)
            #pragma unroll
            for (int k = 0; k < 4; k++) acc[i][j][k] = 0.f;

    load_stage(0, 0);   CP_COMMIT();
    load_stage(1, GBK); CP_COMMIT();

    // ldmatrix per-lane addressing
    const int grp = lane >> 3;
    const int rin = lane & 7;
    const int rowsel = (grp & 1) * 8 + rin;
    const int colsel = (grp >> 1) * 8;

    const int NKC = KDIM / GBK;        // 16
    for (int kc = 0; kc < NKC; kc++) {
        CP_WAIT1();
        __syncthreads();
        if (kc + 2 < NKC) load_stage((kc + 2) % NSTAGES, (kc + 2) * GBK);
        CP_COMMIT();

        const int s = kc % NSTAGES;
        const uint32_t sb = sbase + (uint32_t)(s * STAGE_ELEMS * 2);
        const uint32_t aH = sb;
        const uint32_t aL = sb + A_ELEMS * 2;
        const uint32_t bH = sb + 2 * A_ELEMS * 2;
        const uint32_t bL = sb + (2 * A_ELEMS + B_ELEMS) * 2;

        #pragma unroll
        for (int ks = 0; ks < 2; ks++) {
            const int kb = ks * 16 + colsel;

            // B fragments for this warp's 32 columns (2 x n16)
            uint32_t bh[2][4], bl[2][4];
            #pragma unroll
            for (int p = 0; p < 2; p++) {
                uint32_t off = (uint32_t)(((wn * 32 + p * 16 + rowsel) * RSTRIDE + kb) * 2);
                ldm_x4(bh[p][0], bh[p][1], bh[p][2], bh[p][3], bH + off);
                ldm_x4(bl[p][0], bl[p][1], bl[p][2], bl[p][3], bL + off);
            }

            #pragma unroll
            for (int mt = 0; mt < 4; mt++) {
                uint32_t off = (uint32_t)(((wm * 64 + mt * 16 + rowsel) * RSTRIDE + kb) * 2);
                uint32_t ah[4], al[4];
                ldm_x4(ah[0], ah[1], ah[2], ah[3], aH + off);
                ldm_x4(al[0], al[1], al[2], al[3], aL + off);

                // pass 0: Ah*Bh  (dependency distance 4 between same-acc mmas)
                #pragma unroll
                for (int nt = 0; nt < 4; nt++) {
                    const int p = nt >> 1, o = nt & 1;
                    mma16816(acc[mt][nt], ah, bh[p][0 + o], bh[p][2 + o]);
                }
                // pass 1: Ah*Bl
                #pragma unroll
                for (int nt = 0; nt < 4; nt++) {
                    const int p = nt >> 1, o = nt & 1;
                    mma16816(acc[mt][nt], ah, bl[p][0 + o], bl[p][2 + o]);
                }
                // pass 2: Al*Bh
                #pragma unroll
                for (int nt = 0; nt < 4; nt++) {
                    const int p = nt >> 1, o = nt & 1;
                    mma16816(acc[mt][nt], al, bh[p][0 + o], bh[p][2 + o]);
                }
            }
        }
        __syncthreads();
    }

    // ------------- epilogue -------------
    const int r   = lane >> 2;
    const int cp2 = (lane & 3) * 2;
    #pragma unroll
    for (int mt = 0; mt < 4; mt++) {
        #pragma unroll
        for (int nt = 0; nt < 4; nt++) {
            const int col  = n0 + wn * 32 + nt * 8 + cp2;
            const int row0 = m0 + wm * 64 + mt * 16 + r;
            #pragma unroll
            for (int h = 0; h < 2; h++) {
                const int row = row0 + h * 8;
                const size_t off = (size_t)row * DM + col;
                float v0 = acc[mt][nt][2 * h + 0];
                float v1 = acc[mt][nt][2 * h + 1];
                if (MODE == 1) {
                    v0 = 1.f / (1.f + __expf(-(v0 + bias[col + 0])));
                    v1 = 1.f / (1.f + __expf(-(v1 + bias[col + 1])));
                } else if (MODE == 2) {
                    float2 xv = *(const float2*)&xres[off];
                    float2 gv = *(const float2*)&gate[off];
                    v0 = xv.x + gv.x * v0;
                    v1 = xv.y + gv.y * v1;
                }
                *(float2*)&C[off] = make_float2(v0, v1);
            }
        }
    }
}

// ---------------- S4D diagonal scan (packed f32x2) ------------------------
__global__ __launch_bounds__(128) void scan_kernel(const float* __restrict__ D_p)
{
    __shared__ unsigned long long sp[4][32 * 33];
    const int w    = threadIdx.x >> 5;
    const int lane = threadIdx.x & 31;
    const int d    = blockIdx.x * 4 + w;
    const int b    = blockIdx.y;
    unsigned long long* spw = sp[w];

    const int base = d * SN;
    const unsigned long long ar2  = pk2(g_ar[base + lane],  g_ar[base + 32 + lane]);
    const unsigned long long ai2  = pk2(g_ai[base + lane],  g_ai[base + 32 + lane]);
    const unsigned long long nai2 = pk2(-g_ai[base + lane], -g_ai[base + 32 + lane]);
    const unsigned long long cb2  = pk2(g_cb[base + lane],  g_cb[base + 32 + lane]);
    const float Dp  = D_p[d];

    const float* up = g_u + (size_t)(b * SEQ) * DM + d;
    __nv_bfloat16* yh = g_yh + (size_t)(b * SEQ) * DM + d;
    __nv_bfloat16* yl = g_yl + (size_t)(b * SEQ) * DM + d;

    unsigned long long gr2 = 0ull, gi2 = 0ull;
    float ucur = up[(size_t)lane * DM];

    const int NT = SEQ / 32;   // 64 tiles
    for (int tt = 0; tt < NT; tt++) {
        float unext = 0.f;
        if (tt + 1 < NT) unext = up[(size_t)((tt + 1) * 32 + lane) * DM];

        #pragma unroll
        for (int j = 0; j < 32; j++) {
            float uj = __shfl_sync(0xffffffffu, ucur, j);
            unsigned long long u2  = pk2(uj, uj);
            unsigned long long nr  = fma2(ar2, gr2, fma2(nai2, gi2, mul2(cb2, u2)));
            unsigned long long ni  = fma2(ai2, gr2, mul2(ar2, gi2));
            gr2 = nr; gi2 = ni;
            spw[j * 33 + lane] = nr;
        }
        __syncwarp();

        unsigned long long accA = spw[lane * 33 + 0];
        unsigned long long accB = spw[lane * 33 + 1];
        #pragma unroll
        for (int k2 = 2; k2 < 32; k2 += 2) {
            accA = add2(accA, spw[lane * 33 + k2]);
            accB = add2(accB, spw[lane * 33 + k2 + 1]);
        }
        accA = add2(accA, accB);
        float s0, s1;
        upk2(accA, s0, s1);
        float acc = fmaf(Dp, ucur, s0 + s1);

        const size_t oidx = (size_t)(tt * 32 + lane) * DM;
        __nv_bfloat16 h = __float2bfloat16(acc);
        yh[oidx] = h;
        yl[oidx] = __float2bfloat16(acc - __bfloat162float(h));
        __syncwarp();

        ucur = unext;
    }
}

// ---------------- launch --------------------------------------------------
extern "C" void kernel_launch(void* const* d_in, const int* in_sizes, int n_in,
                              void* d_out, int out_size)
{
    const float* x          = (const float*)d_in[0];
    const float* log_A_real = (const float*)d_in[1];
    const float* A_imag     = (const float*)d_in[2];
    const float* B_p        = (const float*)d_in[3];
    const float* C_p        = (const float*)d_in[4];
    const float* D_p        = (const float*)d_in[5];
    const float* log_dt     = (const float*)d_in[6];
    const float* W_in       = (const float*)d_in[7];
    const float* W_out      = (const float*)d_in[8];
    const float* W_gate     = (const float*)d_in[9];
    const float* b_gate     = (const float*)d_in[10];
    float* out = (float*)d_out;

    float *pu, *pg;
    __nv_bfloat16 *xh, *xl, *yh, *yl, *wih, *wil, *wgh, *wgl, *woh, *wol;
    cudaGetSymbolAddress((void**)&pu,  g_u);
    cudaGetSymbolAddress((void**)&pg,  g_gate);
    cudaGetSymbolAddress((void**)&xh,  g_xh);
    cudaGetSymbolAddress((void**)&xl,  g_xl);
    cudaGetSymbolAddress((void**)&yh,  g_yh);
    cudaGetSymbolAddress((void**)&yl,  g_yl);
    cudaGetSymbolAddress((void**)&wih, g_wih);
    cudaGetSymbolAddress((void**)&wil, g_wil);
    cudaGetSymbolAddress((void**)&wgh, g_wgh);
    cudaGetSymbolAddress((void**)&wgl, g_wgl);
    cudaGetSymbolAddress((void**)&woh, g_woh);
    cudaGetSymbolAddress((void**)&wol, g_wol);

    cudaFuncSetAttribute(gemm_bf16x3_kernel<0>,
                         cudaFuncAttributeMaxDynamicSharedMemorySize, GEMM_SMEM);
    cudaFuncSetAttribute(gemm_bf16x3_kernel<1>,
                         cudaFuncAttributeMaxDynamicSharedMemorySize, GEMM_SMEM);
    cudaFuncSetAttribute(gemm_bf16x3_kernel<2>,
                         cudaFuncAttributeMaxDynamicSharedMemorySize, GEMM_SMEM);

    param_kernel<<<(DM * SN + 255) / 256, 256>>>(log_A_real, A_imag, B_p, C_p, log_dt);

    split_kernel<<<(M_TOT * DM + 255) / 256, 256>>>(x, xh, xl, M_TOT * DM);
    split3_kernel<<<(3 * DM * DM + 255) / 256, 256>>>(W_in, W_gate, W_out,
                                                      wih, wil, wgh, wgl, woh, wol);

    dim3 gg(DM / GBN, M_TOT / GBM);   // (4, 32) = 128 CTAs
    gemm_bf16x3_kernel<0><<<gg, 512, GEMM_SMEM>>>(xh, xl, wih, wil, pu,
                                                  nullptr, nullptr, nullptr);
    gemm_bf16x3_kernel<1><<<gg, 512, GEMM_SMEM>>>(xh, xl, wgh, wgl, pg,
                                                  b_gate, nullptr, nullptr);

    scan_kernel<<<dim3(DM / 4, NBATCH), 128>>>(D_p);

    gemm_bf16x3_kernel<2><<<gg, 512, GEMM_SMEM>>>(yh, yl, woh, wol, out,
                                                  nullptr, x, pg);
}

// round 6
// speedup vs baseline: 1.4632x; 1.1342x over previous
#include <cuda_runtime.h>
#include <cuda_bf16.h>
#include <cstdint>

#define DM 512
#define SN 64
#define NBATCH 4
#define SEQ 2048
#define M_TOT (NBATCH*SEQ)   // 8192
#define KDIM 512

// ---------------- scratch (no runtime allocation allowed) ----------------
__device__ float g_u[M_TOT * DM];        // u [bt, d]
__device__ float g_ut[M_TOT * DM];       // u transposed [b, d, t]
__device__ float g_gate[M_TOT * DM];
__device__ __nv_bfloat16 g_xh[M_TOT * DM];
__device__ __nv_bfloat16 g_xl[M_TOT * DM];
__device__ __nv_bfloat16 g_yht[M_TOT * DM];  // y hi, transposed [b, d, t]
__device__ __nv_bfloat16 g_ylt[M_TOT * DM];  // y lo, transposed
__device__ __nv_bfloat16 g_yh[M_TOT * DM];   // y hi [bt, d]
__device__ __nv_bfloat16 g_yl[M_TOT * DM];
__device__ __nv_bfloat16 g_wih[DM * DM], g_wil[DM * DM];
__device__ __nv_bfloat16 g_wgh[DM * DM], g_wgl[DM * DM];
__device__ __nv_bfloat16 g_woh[DM * DM], g_wol[DM * DM];
__device__ float g_ar[DM * SN];
__device__ float g_ai[DM * SN];
__device__ float g_cb[DM * SN];

// ---------------- f32x2 packed helpers ------------------------------------
__device__ __forceinline__ unsigned long long pk2(float a, float b) {
    unsigned long long r;
    asm("mov.b64 %0, {%1, %2};" : "=l"(r) : "f"(a), "f"(b));
    return r;
}
__device__ __forceinline__ void upk2(unsigned long long v, float& a, float& b) {
    asm("mov.b64 {%0, %1}, %2;" : "=f"(a), "=f"(b) : "l"(v));
}
__device__ __forceinline__ unsigned long long fma2(unsigned long long a,
                                                   unsigned long long b,
                                                   unsigned long long c) {
    unsigned long long r;
    asm("fma.rn.f32x2 %0, %1, %2, %3;" : "=l"(r) : "l"(a), "l"(b), "l"(c));
    return r;
}
__device__ __forceinline__ unsigned long long mul2(unsigned long long a,
                                                   unsigned long long b) {
    unsigned long long r;
    asm("mul.rn.f32x2 %0, %1, %2;" : "=l"(r) : "l"(a), "l"(b));
    return r;
}
__device__ __forceinline__ unsigned long long add2(unsigned long long a,
                                                   unsigned long long b) {
    unsigned long long r;
    asm("add.rn.f32x2 %0, %1, %2;" : "=l"(r) : "l"(a), "l"(b));
    return r;
}

// ---------------- parameter precompute -----------------------------------
__global__ void param_kernel(const float* __restrict__ log_A_real,
                             const float* __restrict__ A_imag,
                             const float* __restrict__ B_p,
                             const float* __restrict__ C_p,
                             const float* __restrict__ log_dt)
{
    int idx = blockIdx.x * blockDim.x + threadIdx.x;
    if (idx >= DM * SN) return;
    int d = idx / SN;
    float dt  = expf(log_dt[d]);
    float are = -expf(log_A_real[idx]);
    float aim = A_imag[idx];
    float r = expf(are * dt);
    float s, c;
    sincosf(aim * dt, &s, &c);
    g_ar[idx] = r * c;
    g_ai[idx] = r * s;
    g_cb[idx] = C_p[idx] * B_p[idx] * dt;
}

// ---------------- fp32 -> bf16 hi/lo splits --------------------------------
__global__ void split_kernel(const float* __restrict__ in,
                             __nv_bfloat16* __restrict__ hi,
                             __nv_bfloat16* __restrict__ lo, int n)
{
    int i = blockIdx.x * blockDim.x + threadIdx.x;
    if (i >= n) return;
    float v = in[i];
    __nv_bfloat16 h = __float2bfloat16(v);
    hi[i] = h;
    lo[i] = __float2bfloat16(v - __bfloat162float(h));
}

__global__ void split3_kernel(const float* __restrict__ w0, const float* __restrict__ w1,
                              const float* __restrict__ w2,
                              __nv_bfloat16* __restrict__ h0, __nv_bfloat16* __restrict__ l0,
                              __nv_bfloat16* __restrict__ h1, __nv_bfloat16* __restrict__ l1,
                              __nv_bfloat16* __restrict__ h2, __nv_bfloat16* __restrict__ l2)
{
    int i = blockIdx.x * blockDim.x + threadIdx.x;
    if (i >= 3 * DM * DM) return;
    int which = i / (DM * DM);
    int j = i - which * (DM * DM);
    const float* src = (which == 0) ? w0 : (which == 1) ? w1 : w2;
    __nv_bfloat16* hh = (which == 0) ? h0 : (which == 1) ? h1 : h2;
    __nv_bfloat16* ll = (which == 0) ? l0 : (which == 1) ? l1 : l2;
    float v = src[j];
    __nv_bfloat16 h = __float2bfloat16(v);
    hh[j] = h;
    ll[j] = __float2bfloat16(v - __bfloat162float(h));
}

// ---------------- transposes ----------------------------------------------
// u [b*SEQ + t, d] -> u_T [(b*DM + d)*SEQ + t]
__global__ void transpose_u_kernel()
{
    __shared__ float tile[32][33];
    const int b  = blockIdx.z;
    const int d0 = blockIdx.x * 32;
    const int t0 = blockIdx.y * 32;
    const int tx = threadIdx.x, ty = threadIdx.y;   // 32 x 8
    #pragma unroll
    for (int i = 0; i < 4; i++)
        tile[ty + i * 8][tx] = g_u[(size_t)(b * SEQ + t0 + ty + i * 8) * DM + d0 + tx];
    __syncthreads();
    #pragma unroll
    for (int i = 0; i < 4; i++)
        g_ut[(size_t)(b * DM + d0 + ty + i * 8) * SEQ + t0 + tx] = tile[tx][ty + i * 8];
}

// y_T hi/lo [(b*DM+d)*SEQ + t] -> y hi/lo [b*SEQ + t, d]
__global__ void transpose_y_kernel()
{
    __shared__ __nv_bfloat16 th[32][34];
    __shared__ __nv_bfloat16 tl[32][34];
    const int b  = blockIdx.z;
    const int d0 = blockIdx.x * 32;
    const int t0 = blockIdx.y * 32;
    const int tx = threadIdx.x, ty = threadIdx.y;   // 32 x 8
    #pragma unroll
    for (int i = 0; i < 4; i++) {
        const size_t src = (size_t)(b * DM + d0 + ty + i * 8) * SEQ + t0 + tx;
        th[ty + i * 8][tx] = g_yht[src];
        tl[ty + i * 8][tx] = g_ylt[src];
    }
    __syncthreads();
    #pragma unroll
    for (int i = 0; i < 4; i++) {
        const size_t dst = (size_t)(b * SEQ + t0 + ty + i * 8) * DM + d0 + tx;
        g_yh[dst] = th[tx][ty + i * 8];
        g_yl[dst] = tl[tx][ty + i * 8];
    }
}

// ============================================================================
// bf16x3 mma.sync GEMM, tile 128x128, 256 threads (8 warps, 2x4), 2-stage,
// 2 CTAs/SM.  C = A[M,K] * B[N,K]^T with A~Ah+Al, B~Bh+Bl.
// MODE 0 (fused x-proj): grid.x=8; half = blockIdx.x>>2 selects (W_in -> u,
//         plain) or (W_gate -> gate, sigmoid+bias); n0 = (blockIdx.x&3)*128.
// MODE 2 (out-proj): grid.x=4; C = xres + gate * acc.
// ============================================================================
#define GBM 128
#define GBN 128
#define GBK 32
#define RSTRIDE 40
#define A_ELEMS (GBM * RSTRIDE)               // 5120 per split
#define B_ELEMS (GBN * RSTRIDE)               // 5120 per split
#define STAGE_ELEMS (2*A_ELEMS + 2*B_ELEMS)   // 20480
#define NSTAGES 2
#define GEMM_SMEM (NSTAGES * STAGE_ELEMS * 2) // 81920 B

__device__ __forceinline__ void ldm_x4(uint32_t& r0, uint32_t& r1,
                                       uint32_t& r2, uint32_t& r3, uint32_t addr)
{
    asm volatile("ldmatrix.sync.aligned.m8n8.x4.shared.b16 {%0,%1,%2,%3}, [%4];"
                 : "=r"(r0), "=r"(r1), "=r"(r2), "=r"(r3) : "r"(addr));
}

__device__ __forceinline__ void mma16816(float* c, const uint32_t* a,
                                         uint32_t b0, uint32_t b1)
{
    asm volatile(
        "mma.sync.aligned.m16n8k16.row.col.f32.bf16.bf16.f32 "
        "{%0,%1,%2,%3}, {%4,%5,%6,%7}, {%8,%9}, {%0,%1,%2,%3};"
        : "+f"(c[0]), "+f"(c[1]), "+f"(c[2]), "+f"(c[3])
        : "r"(a[0]), "r"(a[1]), "r"(a[2]), "r"(a[3]), "r"(b0), "r"(b1));
}

#define CP16(dst, src) \
    asm volatile("cp.async.cg.shared.global [%0], [%1], 16;" :: "r"(dst), "l"(src))
#define CP_COMMIT() asm volatile("cp.async.commit_group;")
#define CP_WAIT1()  asm volatile("cp.async.wait_group 1;")

template<int MODE>
__global__ __launch_bounds__(256, 2) void gemm_bf16x3_kernel(
    const __nv_bfloat16* __restrict__ Ah, const __nv_bfloat16* __restrict__ Al,
    const __nv_bfloat16* __restrict__ B0h, const __nv_bfloat16* __restrict__ B0l,
    const __nv_bfloat16* __restrict__ B1h, const __nv_bfloat16* __restrict__ B1l,
    float* __restrict__ C0, float* __restrict__ C1,
    const float* __restrict__ bias,
    const float* __restrict__ xres, const float* __restrict__ gate)
{
    extern __shared__ __nv_bfloat16 smem[];
    const uint32_t sbase = (uint32_t)__cvta_generic_to_shared(smem);

    const int tid  = threadIdx.x;
    const int lane = tid & 31;
    const int warp = tid >> 5;
    const int wm   = warp & 1;        // 0..1 -> 64-row block
    const int wn   = warp >> 1;       // 0..3 -> 32-col block
    const int m0   = blockIdx.y * GBM;

    int half, n0;
    const __nv_bfloat16 *Bh, *Bl;
    float* C;
    if (MODE == 0) {
        half = blockIdx.x >> 2;
        n0   = (blockIdx.x & 3) * GBN;
        Bh = half ? B1h : B0h;  Bl = half ? B1l : B0l;
        C  = half ? C1 : C0;
    } else {
        half = 0;
        n0 = blockIdx.x * GBN;
        Bh = B0h; Bl = B0l; C = C0;
    }

    // cp.async mapping: 256 threads, 8 chunks each
    const int arow = tid >> 2;        // 0..63
    const int ac   = (tid & 3) * 8;   // 0,8,16,24 bf16 elems

    const __nv_bfloat16* gAh0 = Ah + (size_t)(m0 + arow)      * KDIM + ac;
    const __nv_bfloat16* gAh1 = Ah + (size_t)(m0 + arow + 64) * KDIM + ac;
    const __nv_bfloat16* gAl0 = Al + (size_t)(m0 + arow)      * KDIM + ac;
    const __nv_bfloat16* gAl1 = Al + (size_t)(m0 + arow + 64) * KDIM + ac;
    const __nv_bfloat16* gBh0 = Bh + (size_t)(n0 + arow)      * KDIM + ac;
    const __nv_bfloat16* gBh1 = Bh + (size_t)(n0 + arow + 64) * KDIM + ac;
    const __nv_bfloat16* gBl0 = Bl + (size_t)(n0 + arow)      * KDIM + ac;
    const __nv_bfloat16* gBl1 = Bl + (size_t)(n0 + arow + 64) * KDIM + ac;

    const uint32_t dR0 = (uint32_t)((arow        * RSTRIDE + ac) * 2);
    const uint32_t dR1 = (uint32_t)(((arow + 64) * RSTRIDE + ac) * 2);

    auto load_stage = [&](int s, int kk) {
        uint32_t sb = sbase + (uint32_t)(s * STAGE_ELEMS * 2);
        uint32_t aH = sb;
        uint32_t aL = sb + A_ELEMS * 2;
        uint32_t bH = sb + 2 * A_ELEMS * 2;
        uint32_t bL = sb + (2 * A_ELEMS + B_ELEMS) * 2;
        CP16(aH + dR0, gAh0 + kk);
        CP16(aH + dR1, gAh1 + kk);
        CP16(aL + dR0, gAl0 + kk);
        CP16(aL + dR1, gAl1 + kk);
        CP16(bH + dR0, gBh0 + kk);
        CP16(bH + dR1, gBh1 + kk);
        CP16(bL + dR0, gBl0 + kk);
        CP16(bL + dR1, gBl1 + kk);
    };

    float acc[4][4][4];
    #pragma unroll
    for (int i = 0; i < 4; i++)
        #pragma unroll
        for (int j = 0; j < 4; j++)
            #pragma unroll
            for (int k = 0; k < 4; k++) acc[i][j][k] = 0.f;

    load_stage(0, 0);   CP_COMMIT();
    load_stage(1, GBK); CP_COMMIT();

    const int grp = lane >> 3;
    const int rin = lane & 7;
    const int rowsel = (grp & 1) * 8 + rin;
    const int colsel = (grp >> 1) * 8;

    const int NKC = KDIM / GBK;        // 16
    for (int kc = 0; kc < NKC; kc++) {
        CP_WAIT1();
        __syncthreads();

        const int s = kc & 1;
        const uint32_t sb = sbase + (uint32_t)(s * STAGE_ELEMS * 2);
        const uint32_t aH = sb;
        const uint32_t aL = sb + A_ELEMS * 2;
        const uint32_t bH = sb + 2 * A_ELEMS * 2;
        const uint32_t bL = sb + (2 * A_ELEMS + B_ELEMS) * 2;

        #pragma unroll
        for (int ks = 0; ks < 2; ks++) {
            const int kb = ks * 16 + colsel;

            uint32_t bh[2][4], bl[2][4];
            #pragma unroll
            for (int p = 0; p < 2; p++) {
                uint32_t off = (uint32_t)(((wn * 32 + p * 16 + rowsel) * RSTRIDE + kb) * 2);
                ldm_x4(bh[p][0], bh[p][1], bh[p][2], bh[p][3], bH + off);
                ldm_x4(bl[p][0], bl[p][1], bl[p][2], bl[p][3], bL + off);
            }

            #pragma unroll
            for (int mt = 0; mt < 4; mt++) {
                uint32_t off = (uint32_t)(((wm * 64 + mt * 16 + rowsel) * RSTRIDE + kb) * 2);
                uint32_t ah[4], al[4];
                ldm_x4(ah[0], ah[1], ah[2], ah[3], aH + off);
                ldm_x4(al[0], al[1], al[2], al[3], aL + off);

                #pragma unroll
                for (int nt = 0; nt < 4; nt++) {
                    const int p = nt >> 1, o = nt & 1;
                    mma16816(acc[mt][nt], ah, bh[p][0 + o], bh[p][2 + o]);
                }
                #pragma unroll
                for (int nt = 0; nt < 4; nt++) {
                    const int p = nt >> 1, o = nt & 1;
                    mma16816(acc[mt][nt], ah, bl[p][0 + o], bl[p][2 + o]);
                }
                #pragma unroll
                for (int nt = 0; nt < 4; nt++) {
                    const int p = nt >> 1, o = nt & 1;
                    mma16816(acc[mt][nt], al, bh[p][0 + o], bh[p][2 + o]);
                }
            }
        }
        __syncthreads();
        if (kc + 2 < NKC) load_stage(s, (kc + 2) * GBK);
        CP_COMMIT();
    }

    // ------------- epilogue -------------
    const int r   = lane >> 2;
    const int cp2 = (lane & 3) * 2;
    #pragma unroll
    for (int mt = 0; mt < 4; mt++) {
        #pragma unroll
        for (int nt = 0; nt < 4; nt++) {
            const int col  = n0 + wn * 32 + nt * 8 + cp2;
            const int row0 = m0 + wm * 64 + mt * 16 + r;
            #pragma unroll
            for (int h = 0; h < 2; h++) {
                const int row = row0 + h * 8;
                const size_t off = (size_t)row * DM + col;
                float v0 = acc[mt][nt][2 * h + 0];
                float v1 = acc[mt][nt][2 * h + 1];
                if (MODE == 0) {
                    if (half == 1) {
                        v0 = 1.f / (1.f + __expf(-(v0 + bias[col + 0])));
                        v1 = 1.f / (1.f + __expf(-(v1 + bias[col + 1])));
                    }
                } else {
                    float2 xv = *(const float2*)&xres[off];
                    float2 gv = *(const float2*)&gate[off];
                    v0 = xv.x + gv.x * v0;
                    v1 = xv.y + gv.y * v1;
                }
                *(float2*)&C[off] = make_float2(v0, v1);
            }
        }
    }
}

// ---------------- S4D diagonal scan (packed f32x2, coalesced I/O) ----------
__global__ __launch_bounds__(128) void scan_kernel(const float* __restrict__ D_p)
{
    __shared__ unsigned long long sp[4][32 * 33];
    const int w    = threadIdx.x >> 5;
    const int lane = threadIdx.x & 31;
    const int d    = blockIdx.x * 4 + w;
    const int b    = blockIdx.y;
    unsigned long long* spw = sp[w];

    const int base = d * SN;
    const unsigned long long ar2  = pk2(g_ar[base + lane],  g_ar[base + 32 + lane]);
    const unsigned long long ai2  = pk2(g_ai[base + lane],  g_ai[base + 32 + lane]);
    const unsigned long long nai2 = pk2(-g_ai[base + lane], -g_ai[base + 32 + lane]);
    const unsigned long long cb2  = pk2(g_cb[base + lane],  g_cb[base + 32 + lane]);
    const float Dp  = D_p[d];

    const float* up = g_ut + (size_t)(b * DM + d) * SEQ;
    __nv_bfloat16* yh = g_yht + (size_t)(b * DM + d) * SEQ;
    __nv_bfloat16* yl = g_ylt + (size_t)(b * DM + d) * SEQ;

    unsigned long long gr2 = 0ull, gi2 = 0ull;
    float ucur = up[lane];

    const int NT = SEQ / 32;   // 64 tiles
    for (int tt = 0; tt < NT; tt++) {
        float unext = 0.f;
        if (tt + 1 < NT) unext = up[(tt + 1) * 32 + lane];

        #pragma unroll
        for (int j = 0; j < 32; j++) {
            float uj = __shfl_sync(0xffffffffu, ucur, j);
            unsigned long long u2  = pk2(uj, uj);
            unsigned long long nr  = fma2(ar2, gr2, fma2(nai2, gi2, mul2(cb2, u2)));
            unsigned long long ni  = fma2(ai2, gr2, mul2(ar2, gi2));
            gr2 = nr; gi2 = ni;
            spw[j * 33 + lane] = nr;
        }
        __syncwarp();

        unsigned long long accA = spw[lane * 33 + 0];
        unsigned long long accB = spw[lane * 33 + 1];
        #pragma unroll
        for (int k2 = 2; k2 < 32; k2 += 2) {
            accA = add2(accA, spw[lane * 33 + k2]);
            accB = add2(accB, spw[lane * 33 + k2 + 1]);
        }
        accA = add2(accA, accB);
        float s0, s1;
        upk2(accA, s0, s1);
        float acc = fmaf(Dp, ucur, s0 + s1);

        const int oidx = tt * 32 + lane;
        __nv_bfloat16 h = __float2bfloat16(acc);
        yh[oidx] = h;
        yl[oidx] = __float2bfloat16(acc - __bfloat162float(h));
        __syncwarp();

        ucur = unext;
    }
}

// ---------------- launch --------------------------------------------------
extern "C" void kernel_launch(void* const* d_in, const int* in_sizes, int n_in,
                              void* d_out, int out_size)
{
    const float* x          = (const float*)d_in[0];
    const float* log_A_real = (const float*)d_in[1];
    const float* A_imag     = (const float*)d_in[2];
    const float* B_p        = (const float*)d_in[3];
    const float* C_p        = (const float*)d_in[4];
    const float* D_p        = (const float*)d_in[5];
    const float* log_dt     = (const float*)d_in[6];
    const float* W_in       = (const float*)d_in[7];
    const float* W_out      = (const float*)d_in[8];
    const float* W_gate     = (const float*)d_in[9];
    const float* b_gate     = (const float*)d_in[10];
    float* out = (float*)d_out;

    float *pu, *pg;
    __nv_bfloat16 *xh, *xl, *yh, *yl, *wih, *wil, *wgh, *wgl, *woh, *wol;
    cudaGetSymbolAddress((void**)&pu,  g_u);
    cudaGetSymbolAddress((void**)&pg,  g_gate);
    cudaGetSymbolAddress((void**)&xh,  g_xh);
    cudaGetSymbolAddress((void**)&xl,  g_xl);
    cudaGetSymbolAddress((void**)&yh,  g_yh);
    cudaGetSymbolAddress((void**)&yl,  g_yl);
    cudaGetSymbolAddress((void**)&wih, g_wih);
    cudaGetSymbolAddress((void**)&wil, g_wil);
    cudaGetSymbolAddress((void**)&wgh, g_wgh);
    cudaGetSymbolAddress((void**)&wgl, g_wgl);
    cudaGetSymbolAddress((void**)&woh, g_woh);
    cudaGetSymbolAddress((void**)&wol, g_wol);

    cudaFuncSetAttribute(gemm_bf16x3_kernel<0>,
                         cudaFuncAttributeMaxDynamicSharedMemorySize, GEMM_SMEM);
    cudaFuncSetAttribute(gemm_bf16x3_kernel<2>,
                         cudaFuncAttributeMaxDynamicSharedMemorySize, GEMM_SMEM);

    param_kernel<<<(DM * SN + 255) / 256, 256>>>(log_A_real, A_imag, B_p, C_p, log_dt);

    split_kernel<<<(M_TOT * DM + 255) / 256, 256>>>(x, xh, xl, M_TOT * DM);
    split3_kernel<<<(3 * DM * DM + 255) / 256, 256>>>(W_in, W_gate, W_out,
                                                      wih, wil, wgh, wgl, woh, wol);

    // fused input/gate projection: grid.x = 8 (4 N-tiles x 2 weight halves)
    gemm_bf16x3_kernel<0><<<dim3(8, M_TOT / GBM), 256, GEMM_SMEM>>>(
        xh, xl, wih, wil, wgh, wgl, pu, pg, b_gate, nullptr, nullptr);

    transpose_u_kernel<<<dim3(DM / 32, SEQ / 32, NBATCH), dim3(32, 8)>>>();

    scan_kernel<<<dim3(DM / 4, NBATCH), 128>>>(D_p);

    transpose_y_kernel<<<dim3(DM / 32, SEQ / 32, NBATCH), dim3(32, 8)>>>();

    gemm_bf16x3_kernel<2><<<dim3(4, M_TOT / GBM), 256, GEMM_SMEM>>>(
        yh, yl, woh, wol, nullptr, nullptr, out, nullptr, nullptr, x, pg);
}

// round 8
// speedup vs baseline: 1.7398x; 1.1890x over previous
#include <cuda_runtime.h>
#include <cuda_bf16.h>
#include <cuda_fp16.h>
#include <cstdint>

#define DM 512
#define SN 64
#define NBATCH 4
#define SEQ 2048
#define M_TOT (NBATCH*SEQ)   // 8192
#define KDIM 512

// ---------------- scratch (no runtime allocation allowed) ----------------
__device__ float g_ut[M_TOT * DM];       // u transposed [b, d, t] (fp32)
__device__ float g_gate[M_TOT * DM];     // sigmoid gate [bt, d]
__device__ __half g_xh[M_TOT * DM];
__device__ __half g_xl[M_TOT * DM];
__device__ __half g_yht[M_TOT * DM];     // y hi, transposed [b, d, t]
__device__ __half g_ylt[M_TOT * DM];     // y lo, transposed
__device__ __half g_yh[M_TOT * DM];      // y hi [bt, d]
__device__ __half g_yl[M_TOT * DM];
__device__ __half g_wi[DM * DM];
__device__ __half g_wg[DM * DM];
__device__ __half g_wo[DM * DM];
__device__ float g_ar[DM * SN];
__device__ float g_ai[DM * SN];
__device__ float g_cb[DM * SN];

// ---------------- f32x2 packed helpers ------------------------------------
__device__ __forceinline__ unsigned long long pk2(float a, float b) {
    unsigned long long r;
    asm("mov.b64 %0, {%1, %2};" : "=l"(r) : "f"(a), "f"(b));
    return r;
}
__device__ __forceinline__ void upk2(unsigned long long v, float& a, float& b) {
    asm("mov.b64 {%0, %1}, %2;" : "=f"(a), "=f"(b) : "l"(v));
}
__device__ __forceinline__ unsigned long long fma2(unsigned long long a,
                                                   unsigned long long b,
                                                   unsigned long long c) {
    unsigned long long r;
    asm("fma.rn.f32x2 %0, %1, %2, %3;" : "=l"(r) : "l"(a), "l"(b), "l"(c));
    return r;
}
__device__ __forceinline__ unsigned long long mul2(unsigned long long a,
                                                   unsigned long long b) {
    unsigned long long r;
    asm("mul.rn.f32x2 %0, %1, %2;" : "=l"(r) : "l"(a), "l"(b));
    return r;
}
__device__ __forceinline__ unsigned long long add2(unsigned long long a,
                                                   unsigned long long b) {
    unsigned long long r;
    asm("add.rn.f32x2 %0, %1, %2;" : "=l"(r) : "l"(a), "l"(b));
    return r;
}

// ---------------- parameter precompute -----------------------------------
__global__ void param_kernel(const float* __restrict__ log_A_real,
                             const float* __restrict__ A_imag,
                             const float* __restrict__ B_p,
                             const float* __restrict__ C_p,
                             const float* __restrict__ log_dt)
{
    int idx = blockIdx.x * blockDim.x + threadIdx.x;
    if (idx >= DM * SN) return;
    int d = idx / SN;
    float dt  = expf(log_dt[d]);
    float are = -expf(log_A_real[idx]);
    float aim = A_imag[idx];
    float r = expf(are * dt);
    float s, c;
    sincosf(aim * dt, &s, &c);
    g_ar[idx] = r * c;
    g_ai[idx] = r * s;
    g_cb[idx] = C_p[idx] * B_p[idx] * dt;
}

// ---------------- fp32 -> fp16 hi/lo split --------------------------------
__global__ void split_kernel(const float* __restrict__ in,
                             __half* __restrict__ hi,
                             __half* __restrict__ lo, int n)
{
    int i = blockIdx.x * blockDim.x + threadIdx.x;
    if (i >= n) return;
    float v = in[i];
    __half h = __float2half(v);
    hi[i] = h;
    lo[i] = __float2half(v - __half2float(h));
}

// three weight matrices -> single fp16 each
__global__ void wcvt_kernel(const float* __restrict__ w0, const float* __restrict__ w1,
                            const float* __restrict__ w2,
                            __half* __restrict__ o0, __half* __restrict__ o1,
                            __half* __restrict__ o2)
{
    int i = blockIdx.x * blockDim.x + threadIdx.x;
    if (i >= 3 * DM * DM) return;
    int which = i / (DM * DM);
    int j = i - which * (DM * DM);
    const float* src = (which == 0) ? w0 : (which == 1) ? w1 : w2;
    __half* dst      = (which == 0) ? o0 : (which == 1) ? o1 : o2;
    dst[j] = __float2half(src[j]);
}

// ---------------- y transpose back: [b,d,t] -> [bt,d] (fp16 hi/lo) ---------
__global__ void transpose_y_kernel()
{
    __shared__ __half th[32][34];
    __shared__ __half tl[32][34];
    const int b  = blockIdx.z;
    const int d0 = blockIdx.x * 32;
    const int t0 = blockIdx.y * 32;
    const int tx = threadIdx.x, ty = threadIdx.y;   // 32 x 8
    #pragma unroll
    for (int i = 0; i < 4; i++) {
        const size_t src = (size_t)(b * DM + d0 + ty + i * 8) * SEQ + t0 + tx;
        th[ty + i * 8][tx] = g_yht[src];
        tl[ty + i * 8][tx] = g_ylt[src];
    }
    __syncthreads();
    #pragma unroll
    for (int i = 0; i < 4; i++) {
        const size_t dst = (size_t)(b * SEQ + t0 + ty + i * 8) * DM + d0 + tx;
        g_yh[dst] = th[tx][ty + i * 8];
        g_yl[dst] = tl[tx][ty + i * 8];
    }
}

// ============================================================================
// fp16 2-pass mma.sync GEMM: C = A[M,K]*B[N,K]^T,  A ~ Ah+Al (fp16), B fp16.
// acc = Ah*B + Al*B.  Tile 128x128, 256 threads (8 warps 2x4), 2-stage.
// MODE 0 (fused x-proj, grid.x=8): half=blockIdx.x>>2.
//   half 0: W_in -> u, written TRANSPOSED to g_ut[b,d,t] via smem.
//   half 1: W_gate -> sigmoid(acc+bias) -> C1 (g_gate, [bt,d]).
// MODE 2 (out-proj, grid.x=4): C0 = xres + gate * acc.
// ============================================================================
#define GBM 128
#define GBN 128
#define GBK 32
#define RSTRIDE 40
#define PIECE_ELEMS (GBM * RSTRIDE)           // 5120 fp16
#define STAGE_ELEMS (3 * PIECE_ELEMS)         // Ah, Al, B = 15360
#define NSTAGES 2
#define GEMM_SMEM (NSTAGES * STAGE_ELEMS * 2) // 61440 B

__device__ __forceinline__ void ldm_x4(uint32_t& r0, uint32_t& r1,
                                       uint32_t& r2, uint32_t& r3, uint32_t addr)
{
    asm volatile("ldmatrix.sync.aligned.m8n8.x4.shared.b16 {%0,%1,%2,%3}, [%4];"
                 : "=r"(r0), "=r"(r1), "=r"(r2), "=r"(r3) : "r"(addr));
}

__device__ __forceinline__ void mma16816(float* c, const uint32_t* a,
                                         uint32_t b0, uint32_t b1)
{
    asm volatile(
        "mma.sync.aligned.m16n8k16.row.col.f32.f16.f16.f32 "
        "{%0,%1,%2,%3}, {%4,%5,%6,%7}, {%8,%9}, {%0,%1,%2,%3};"
        : "+f"(c[0]), "+f"(c[1]), "+f"(c[2]), "+f"(c[3])
        : "r"(a[0]), "r"(a[1]), "r"(a[2]), "r"(a[3]), "r"(b0), "r"(b1));
}

#define CP16(dst, src) \
    asm volatile("cp.async.cg.shared.global [%0], [%1], 16;" :: "r"(dst), "l"(src))
#define CP_COMMIT() asm volatile("cp.async.commit_group;")
#define CP_WAIT1()  asm volatile("cp.async.wait_group 1;")
#define CP_WAIT0()  asm volatile("cp.async.wait_group 0;")

template<int MODE>
__global__ __launch_bounds__(256, 2) void gemm_fp16x2_kernel(
    const __half* __restrict__ Ah, const __half* __restrict__ Al,
    const __half* __restrict__ B0, const __half* __restrict__ B1,
    float* __restrict__ C1,
    float* __restrict__ C0,
    const float* __restrict__ bias,
    const float* __restrict__ xres, const float* __restrict__ gate)
{
    extern __shared__ __half smem[];
    const uint32_t sbase = (uint32_t)__cvta_generic_to_shared(smem);

    const int tid  = threadIdx.x;
    const int lane = tid & 31;
    const int warp = tid >> 5;
    const int wm   = warp & 1;        // 0..1 -> 64-row block
    const int wn   = warp >> 1;       // 0..3 -> 32-col block
    const int m0   = blockIdx.y * GBM;

    int half, n0;
    const __half* B;
    if (MODE == 0) {
        half = blockIdx.x >> 2;
        n0   = (blockIdx.x & 3) * GBN;
        B    = half ? B1 : B0;
    } else {
        half = 0;
        n0 = blockIdx.x * GBN;
        B = B0;
    }

    // cp.async mapping: 256 threads; per piece each thread covers 2 rows
    const int arow = tid >> 2;        // 0..63
    const int ac   = (tid & 3) * 8;   // 0,8,16,24 fp16 elems

    const __half* gAh0 = Ah + (size_t)(m0 + arow)      * KDIM + ac;
    const __half* gAh1 = Ah + (size_t)(m0 + arow + 64) * KDIM + ac;
    const __half* gAl0 = Al + (size_t)(m0 + arow)      * KDIM + ac;
    const __half* gAl1 = Al + (size_t)(m0 + arow + 64) * KDIM + ac;
    const __half* gB0  = B  + (size_t)(n0 + arow)      * KDIM + ac;
    const __half* gB1  = B  + (size_t)(n0 + arow + 64) * KDIM + ac;

    const uint32_t dR0 = (uint32_t)((arow        * RSTRIDE + ac) * 2);
    const uint32_t dR1 = (uint32_t)(((arow + 64) * RSTRIDE + ac) * 2);

    auto load_stage = [&](int s, int kk) {
        uint32_t sb = sbase + (uint32_t)(s * STAGE_ELEMS * 2);
        uint32_t aH = sb;
        uint32_t aL = sb + PIECE_ELEMS * 2;
        uint32_t bB = sb + 2 * PIECE_ELEMS * 2;
        CP16(aH + dR0, gAh0 + kk);
        CP16(aH + dR1, gAh1 + kk);
        CP16(aL + dR0, gAl0 + kk);
        CP16(aL + dR1, gAl1 + kk);
        CP16(bB + dR0, gB0  + kk);
        CP16(bB + dR1, gB1  + kk);
    };

    float acc[4][4][4];
    #pragma unroll
    for (int i = 0; i < 4; i++)
        #pragma unroll
        for (int j = 0; j < 4; j++)
            #pragma unroll
            for (int k = 0; k < 4; k++) acc[i][j][k] = 0.f;

    load_stage(0, 0);   CP_COMMIT();
    load_stage(1, GBK); CP_COMMIT();

    const int grp = lane >> 3;
    const int rin = lane & 7;
    const int rowsel = (grp & 1) * 8 + rin;
    const int colsel = (grp >> 1) * 8;

    const int NKC = KDIM / GBK;        // 16
    for (int kc = 0; kc < NKC; kc++) {
        CP_WAIT1();
        __syncthreads();

        const int s = kc & 1;
        const uint32_t sb = sbase + (uint32_t)(s * STAGE_ELEMS * 2);
        const uint32_t aH = sb;
        const uint32_t aL = sb + PIECE_ELEMS * 2;
        const uint32_t bB = sb + 2 * PIECE_ELEMS * 2;

        #pragma unroll
        for (int ks = 0; ks < 2; ks++) {
            const int kb = ks * 16 + colsel;

            uint32_t bh[2][4];
            #pragma unroll
            for (int p = 0; p < 2; p++) {
                uint32_t off = (uint32_t)(((wn * 32 + p * 16 + rowsel) * RSTRIDE + kb) * 2);
                ldm_x4(bh[p][0], bh[p][1], bh[p][2], bh[p][3], bB + off);
            }

            #pragma unroll
            for (int mt = 0; mt < 4; mt++) {
                uint32_t off = (uint32_t)(((wm * 64 + mt * 16 + rowsel) * RSTRIDE + kb) * 2);
                uint32_t ah[4], al[4];
                ldm_x4(ah[0], ah[1], ah[2], ah[3], aH + off);
                ldm_x4(al[0], al[1], al[2], al[3], aL + off);

                #pragma unroll
                for (int nt = 0; nt < 4; nt++) {
                    const int p = nt >> 1, o = nt & 1;
                    mma16816(acc[mt][nt], ah, bh[p][0 + o], bh[p][2 + o]);
                }
                #pragma unroll
                for (int nt = 0; nt < 4; nt++) {
                    const int p = nt >> 1, o = nt & 1;
                    mma16816(acc[mt][nt], al, bh[p][0 + o], bh[p][2 + o]);
                }
            }
        }
        __syncthreads();
        if (kc + 2 < NKC) load_stage(s, (kc + 2) * GBK);
        CP_COMMIT();
    }

    const int r   = lane >> 2;
    const int cp2 = (lane & 3) * 2;

    if (MODE == 0 && half == 0) {
        // ---- transposed epilogue: u tile -> g_ut[b, d, t] via smem ----
        CP_WAIT0();
        __syncthreads();
        float* tsm = reinterpret_cast<float*>(smem);   // 64 cols x 132 stride
        const int bb = m0 / SEQ;
        const int t0 = m0 % SEQ;
        #pragma unroll
        for (int round = 0; round < 2; round++) {
            if ((wn >> 1) == round) {
                const int colb = (wn & 1) * 32;
                #pragma unroll
                for (int mt = 0; mt < 4; mt++)
                    #pragma unroll
                    for (int nt = 0; nt < 4; nt++)
                        #pragma unroll
                        for (int h = 0; h < 2; h++) {
                            const int row = wm * 64 + mt * 16 + r + h * 8;
                            const int col = colb + nt * 8 + cp2;
                            tsm[col * 132 + row]       = acc[mt][nt][2 * h + 0];
                            tsm[(col + 1) * 132 + row] = acc[mt][nt][2 * h + 1];
                        }
            }
            __syncthreads();
            const int d0r = n0 + round * 64;
            #pragma unroll
            for (int i = 0; i < 8; i++) {
                const int idx = tid + i * 256;     // 0..2047
                const int c   = idx >> 5;          // 0..63
                const int tq  = idx & 31;          // 0..31
                float4 v = *(float4*)&tsm[c * 132 + tq * 4];
                *(float4*)&g_ut[(size_t)(bb * DM + d0r + c) * SEQ + t0 + tq * 4] = v;
            }
            __syncthreads();
        }
        return;
    }

    // ---- standard epilogues ----
    float* C = (MODE == 0) ? C1 : C0;
    #pragma unroll
    for (int mt = 0; mt < 4; mt++) {
        #pragma unroll
        for (int nt = 0; nt < 4; nt++) {
            const int col  = n0 + wn * 32 + nt * 8 + cp2;
            const int row0 = m0 + wm * 64 + mt * 16 + r;
            #pragma unroll
            for (int h = 0; h < 2; h++) {
                const int row = row0 + h * 8;
                const size_t off = (size_t)row * DM + col;
                float v0 = acc[mt][nt][2 * h + 0];
                float v1 = acc[mt][nt][2 * h + 1];
                if (MODE == 0) {   // gate half
                    v0 = 1.f / (1.f + __expf(-(v0 + bias[col + 0])));
                    v1 = 1.f / (1.f + __expf(-(v1 + bias[col + 1])));
                } else {
                    float2 xv = *(const float2*)&xres[off];
                    float2 gv = *(const float2*)&gate[off];
                    v0 = xv.x + gv.x * v0;
                    v1 = xv.y + gv.y * v1;
                }
                *(float2*)&C[off] = make_float2(v0, v1);
            }
        }
    }
}

// ---------------- S4D diagonal scan (packed f32x2, coalesced I/O) ----------
__global__ __launch_bounds__(128) void scan_kernel(const float* __restrict__ D_p)
{
    __shared__ unsigned long long sp[4][32 * 33];
    const int w    = threadIdx.x >> 5;
    const int lane = threadIdx.x & 31;
    const int d    = blockIdx.x * 4 + w;
    const int b    = blockIdx.y;
    unsigned long long* spw = sp[w];

    const int base = d * SN;
    const unsigned long long ar2  = pk2(g_ar[base + lane],  g_ar[base + 32 + lane]);
    const unsigned long long ai2  = pk2(g_ai[base + lane],  g_ai[base + 32 + lane]);
    const unsigned long long nai2 = pk2(-g_ai[base + lane], -g_ai[base + 32 + lane]);
    const unsigned long long cb2  = pk2(g_cb[base + lane],  g_cb[base + 32 + lane]);
    const float Dp  = D_p[d];

    const float* up = g_ut + (size_t)(b * DM + d) * SEQ;
    __half* yh = g_yht + (size_t)(b * DM + d) * SEQ;
    __half* yl = g_ylt + (size_t)(b * DM + d) * SEQ;

    unsigned long long gr2 = 0ull, gi2 = 0ull;
    float ucur = up[lane];

    const int NT = SEQ / 32;   // 64 tiles
    for (int tt = 0; tt < NT; tt++) {
        float unext = 0.f;
        if (tt + 1 < NT) unext = up[(tt + 1) * 32 + lane];

        #pragma unroll
        for (int j = 0; j < 32; j++) {
            float uj = __shfl_sync(0xffffffffu, ucur, j);
            unsigned long long u2  = pk2(uj, uj);
            unsigned long long nr  = fma2(ar2, gr2, fma2(nai2, gi2, mul2(cb2, u2)));
            unsigned long long ni  = fma2(ai2, gr2, mul2(ar2, gi2));
            gr2 = nr; gi2 = ni;
            spw[j * 33 + lane] = nr;
        }
        __syncwarp();

        unsigned long long accA = spw[lane * 33 + 0];
        unsigned long long accB = spw[lane * 33 + 1];
        #pragma unroll
        for (int k2 = 2; k2 < 32; k2 += 2) {
            accA = add2(accA, spw[lane * 33 + k2]);
            accB = add2(accB, spw[lane * 33 + k2 + 1]);
        }
        accA = add2(accA, accB);
        float s0, s1;
        upk2(accA, s0, s1);
        float acc = fmaf(Dp, ucur, s0 + s1);

        const int oidx = tt * 32 + lane;
        __half h = __float2half(acc);
        yh[oidx] = h;
        yl[oidx] = __float2half(acc - __half2float(h));
        __syncwarp();

        ucur = unext;
    }
}

// ---------------- launch --------------------------------------------------
extern "C" void kernel_launch(void* const* d_in, const int* in_sizes, int n_in,
                              void* d_out, int out_size)
{
    const float* x          = (const float*)d_in[0];
    const float* log_A_real = (const float*)d_in[1];
    const float* A_imag     = (const float*)d_in[2];
    const float* B_p        = (const float*)d_in[3];
    const float* C_p        = (const float*)d_in[4];
    const float* D_p        = (const float*)d_in[5];
    const float* log_dt     = (const float*)d_in[6];
    const float* W_in       = (const float*)d_in[7];
    const float* W_out      = (const float*)d_in[8];
    const float* W_gate     = (const float*)d_in[9];
    const float* b_gate     = (const float*)d_in[10];
    float* out = (float*)d_out;

    float *pg;
    __half *xh, *xl, *yh, *yl, *wi, *wg, *wo;
    cudaGetSymbolAddress((void**)&pg, g_gate);
    cudaGetSymbolAddress((void**)&xh, g_xh);
    cudaGetSymbolAddress((void**)&xl, g_xl);
    cudaGetSymbolAddress((void**)&yh, g_yh);
    cudaGetSymbolAddress((void**)&yl, g_yl);
    cudaGetSymbolAddress((void**)&wi, g_wi);
    cudaGetSymbolAddress((void**)&wg, g_wg);
    cudaGetSymbolAddress((void**)&wo, g_wo);

    cudaFuncSetAttribute(gemm_fp16x2_kernel<0>,
                         cudaFuncAttributeMaxDynamicSharedMemorySize, GEMM_SMEM);
    cudaFuncSetAttribute(gemm_fp16x2_kernel<2>,
                         cudaFuncAttributeMaxDynamicSharedMemorySize, GEMM_SMEM);

    param_kernel<<<(DM * SN + 255) / 256, 256>>>(log_A_real, A_imag, B_p, C_p, log_dt);

    split_kernel<<<(M_TOT * DM + 255) / 256, 256>>>(x, xh, xl, M_TOT * DM);
    wcvt_kernel<<<(3 * DM * DM + 255) / 256, 256>>>(W_in, W_gate, W_out, wi, wg, wo);

    // fused input/gate projection: grid.x = 8 (4 N-tiles x 2 weight halves)
    // half 0 -> g_ut (transposed), half 1 -> g_gate (sigmoid)
    gemm_fp16x2_kernel<0><<<dim3(8, M_TOT / GBM), 256, GEMM_SMEM>>>(
        xh, xl, wi, wg, pg, nullptr, b_gate, nullptr, nullptr);

    scan_kernel<<<dim3(DM / 4, NBATCH), 128>>>(D_p);

    transpose_y_kernel<<<dim3(DM / 32, SEQ / 32, NBATCH), dim3(32, 8)>>>();

    gemm_fp16x2_kernel<2><<<dim3(4, M_TOT / GBM), 256, GEMM_SMEM>>>(
        yh, yl, wo, nullptr, nullptr, out, nullptr, x, pg);
}

// round 9
// speedup vs baseline: 1.8168x; 1.0443x over previous
#include <cuda_runtime.h>
#include <cuda_bf16.h>
#include <cuda_fp16.h>
#include <cstdint>

#define DM 512
#define SN 64
#define NBATCH 4
#define SEQ 2048
#define M_TOT (NBATCH*SEQ)   // 8192
#define KDIM 512

// ---------------- scratch (no runtime allocation allowed) ----------------
__device__ float g_ut[M_TOT * DM];       // u transposed [b, d, t] (fp32)
__device__ float g_gate[M_TOT * DM];     // sigmoid gate [bt, d]
__device__ __half g_xh[M_TOT * DM];
__device__ __half g_xl[M_TOT * DM];
__device__ __half g_yht[M_TOT * DM];     // y hi, transposed [b, d, t]
__device__ __half g_ylt[M_TOT * DM];     // y lo, transposed
__device__ __half g_yh[M_TOT * DM];      // y hi [bt, d]
__device__ __half g_yl[M_TOT * DM];
__device__ __half g_wi[DM * DM];
__device__ __half g_wg[DM * DM];
__device__ __half g_wo[DM * DM];
__device__ float g_ar[DM * SN];
__device__ float g_ai[DM * SN];
__device__ float g_cb[DM * SN];

// ---------------- f32x2 packed helpers ------------------------------------
__device__ __forceinline__ unsigned long long pk2(float a, float b) {
    unsigned long long r;
    asm("mov.b64 %0, {%1, %2};" : "=l"(r) : "f"(a), "f"(b));
    return r;
}
__device__ __forceinline__ void upk2(unsigned long long v, float& a, float& b) {
    asm("mov.b64 {%0, %1}, %2;" : "=f"(a), "=f"(b) : "l"(v));
}
__device__ __forceinline__ unsigned long long fma2(unsigned long long a,
                                                   unsigned long long b,
                                                   unsigned long long c) {
    unsigned long long r;
    asm("fma.rn.f32x2 %0, %1, %2, %3;" : "=l"(r) : "l"(a), "l"(b), "l"(c));
    return r;
}
__device__ __forceinline__ unsigned long long mul2(unsigned long long a,
                                                   unsigned long long b) {
    unsigned long long r;
    asm("mul.rn.f32x2 %0, %1, %2;" : "=l"(r) : "l"(a), "l"(b));
    return r;
}
__device__ __forceinline__ unsigned long long add2(unsigned long long a,
                                                   unsigned long long b) {
    unsigned long long r;
    asm("add.rn.f32x2 %0, %1, %2;" : "=l"(r) : "l"(a), "l"(b));
    return r;
}

// ---------------- parameter precompute -----------------------------------
__global__ void param_kernel(const float* __restrict__ log_A_real,
                             const float* __restrict__ A_imag,
                             const float* __restrict__ B_p,
                             const float* __restrict__ C_p,
                             const float* __restrict__ log_dt)
{
    int idx = blockIdx.x * blockDim.x + threadIdx.x;
    if (idx >= DM * SN) return;
    int d = idx / SN;
    float dt  = expf(log_dt[d]);
    float are = -expf(log_A_real[idx]);
    float aim = A_imag[idx];
    float r = expf(are * dt);
    float s, c;
    sincosf(aim * dt, &s, &c);
    g_ar[idx] = r * c;
    g_ai[idx] = r * s;
    g_cb[idx] = C_p[idx] * B_p[idx] * dt;
}

// ---------------- fp32 -> fp16 hi/lo split --------------------------------
__global__ void split_kernel(const float* __restrict__ in,
                             __half* __restrict__ hi,
                             __half* __restrict__ lo, int n)
{
    int i = blockIdx.x * blockDim.x + threadIdx.x;
    if (i >= n) return;
    float v = in[i];
    __half h = __float2half(v);
    hi[i] = h;
    lo[i] = __float2half(v - __half2float(h));
}

// three weight matrices -> single fp16 each
__global__ void wcvt_kernel(const float* __restrict__ w0, const float* __restrict__ w1,
                            const float* __restrict__ w2,
                            __half* __restrict__ o0, __half* __restrict__ o1,
                            __half* __restrict__ o2)
{
    int i = blockIdx.x * blockDim.x + threadIdx.x;
    if (i >= 3 * DM * DM) return;
    int which = i / (DM * DM);
    int j = i - which * (DM * DM);
    const float* src = (which == 0) ? w0 : (which == 1) ? w1 : w2;
    __half* dst      = (which == 0) ? o0 : (which == 1) ? o1 : o2;
    dst[j] = __float2half(src[j]);
}

// ---------------- y transpose back: [b,d,t] -> [bt,d] (fp16 hi/lo) ---------
__global__ void transpose_y_kernel()
{
    __shared__ __half th[32][34];
    __shared__ __half tl[32][34];
    const int b  = blockIdx.z;
    const int d0 = blockIdx.x * 32;
    const int t0 = blockIdx.y * 32;
    const int tx = threadIdx.x, ty = threadIdx.y;   // 32 x 8
    #pragma unroll
    for (int i = 0; i < 4; i++) {
        const size_t src = (size_t)(b * DM + d0 + ty + i * 8) * SEQ + t0 + tx;
        th[ty + i * 8][tx] = g_yht[src];
        tl[ty + i * 8][tx] = g_ylt[src];
    }
    __syncthreads();
    #pragma unroll
    for (int i = 0; i < 4; i++) {
        const size_t dst = (size_t)(b * SEQ + t0 + ty + i * 8) * DM + d0 + tx;
        g_yh[dst] = th[tx][ty + i * 8];
        g_yl[dst] = tl[tx][ty + i * 8];
    }
}

// ============================================================================
// fp16 2-pass mma.sync GEMM body: C = A[M,K]*B[N,K]^T,  A ~ Ah+Al, B fp16.
// Tile 128x128, 256 threads (8 warps 2x4), 2-stage.
// MODE 0: u -> written TRANSPOSED to g_ut[b,d,t] via smem.
// MODE 1: sigmoid(acc + bias) -> C.
// MODE 2: C = xres + gate * acc.
// ============================================================================
#define GBM 128
#define GBN 128
#define GBK 32
#define RSTRIDE 40
#define PIECE_ELEMS (GBM * RSTRIDE)           // 5120 fp16
#define STAGE_ELEMS (3 * PIECE_ELEMS)         // Ah, Al, B = 15360
#define GEMM_SMEM (2 * STAGE_ELEMS * 2)       // 61440 B
#define SCAN_SMEM (8 * 32 * 33 * 8)           // 67584 B
#define FUSED_SMEM SCAN_SMEM

__device__ __forceinline__ void ldm_x4(uint32_t& r0, uint32_t& r1,
                                       uint32_t& r2, uint32_t& r3, uint32_t addr)
{
    asm volatile("ldmatrix.sync.aligned.m8n8.x4.shared.b16 {%0,%1,%2,%3}, [%4];"
                 : "=r"(r0), "=r"(r1), "=r"(r2), "=r"(r3) : "r"(addr));
}

__device__ __forceinline__ void mma16816(float* c, const uint32_t* a,
                                         uint32_t b0, uint32_t b1)
{
    asm volatile(
        "mma.sync.aligned.m16n8k16.row.col.f32.f16.f16.f32 "
        "{%0,%1,%2,%3}, {%4,%5,%6,%7}, {%8,%9}, {%0,%1,%2,%3};"
        : "+f"(c[0]), "+f"(c[1]), "+f"(c[2]), "+f"(c[3])
        : "r"(a[0]), "r"(a[1]), "r"(a[2]), "r"(a[3]), "r"(b0), "r"(b1));
}

#define CP16(dst, src) \
    asm volatile("cp.async.cg.shared.global [%0], [%1], 16;" :: "r"(dst), "l"(src))
#define CP_COMMIT() asm volatile("cp.async.commit_group;")
#define CP_WAIT1()  asm volatile("cp.async.wait_group 1;")
#define CP_WAIT0()  asm volatile("cp.async.wait_group 0;")

template<int MODE>
__device__ __forceinline__ void gemm_body(
    int bx, int by, char* smem_raw,
    const __half* __restrict__ Ah, const __half* __restrict__ Al,
    const __half* __restrict__ B,
    float* __restrict__ C,
    const float* __restrict__ bias,
    const float* __restrict__ xres, const float* __restrict__ gate)
{
    __half* smem = reinterpret_cast<__half*>(smem_raw);
    const uint32_t sbase = (uint32_t)__cvta_generic_to_shared(smem);

    const int tid  = threadIdx.x;
    const int lane = tid & 31;
    const int warp = tid >> 5;
    const int wm   = warp & 1;
    const int wn   = warp >> 1;
    const int m0   = by * GBM;
    const int n0   = bx * GBN;

    const int arow = tid >> 2;        // 0..63
    const int ac   = (tid & 3) * 8;

    const __half* gAh0 = Ah + (size_t)(m0 + arow)      * KDIM + ac;
    const __half* gAh1 = Ah + (size_t)(m0 + arow + 64) * KDIM + ac;
    const __half* gAl0 = Al + (size_t)(m0 + arow)      * KDIM + ac;
    const __half* gAl1 = Al + (size_t)(m0 + arow + 64) * KDIM + ac;
    const __half* gB0  = B  + (size_t)(n0 + arow)      * KDIM + ac;
    const __half* gB1  = B  + (size_t)(n0 + arow + 64) * KDIM + ac;

    const uint32_t dR0 = (uint32_t)((arow        * RSTRIDE + ac) * 2);
    const uint32_t dR1 = (uint32_t)(((arow + 64) * RSTRIDE + ac) * 2);

    auto load_stage = [&](int s, int kk) {
        uint32_t sb = sbase + (uint32_t)(s * STAGE_ELEMS * 2);
        uint32_t aH = sb;
        uint32_t aL = sb + PIECE_ELEMS * 2;
        uint32_t bB = sb + 2 * PIECE_ELEMS * 2;
        CP16(aH + dR0, gAh0 + kk);
        CP16(aH + dR1, gAh1 + kk);
        CP16(aL + dR0, gAl0 + kk);
        CP16(aL + dR1, gAl1 + kk);
        CP16(bB + dR0, gB0  + kk);
        CP16(bB + dR1, gB1  + kk);
    };

    float acc[4][4][4];
    #pragma unroll
    for (int i = 0; i < 4; i++)
        #pragma unroll
        for (int j = 0; j < 4; j++)
            #pragma unroll
            for (int k = 0; k < 4; k++) acc[i][j][k] = 0.f;

    load_stage(0, 0);   CP_COMMIT();
    load_stage(1, GBK); CP_COMMIT();

    const int grp = lane >> 3;
    const int rin = lane & 7;
    const int rowsel = (grp & 1) * 8 + rin;
    const int colsel = (grp >> 1) * 8;

    const int NKC = KDIM / GBK;        // 16
    for (int kc = 0; kc < NKC; kc++) {
        CP_WAIT1();
        __syncthreads();

        const int s = kc & 1;
        const uint32_t sb = sbase + (uint32_t)(s * STAGE_ELEMS * 2);
        const uint32_t aH = sb;
        const uint32_t aL = sb + PIECE_ELEMS * 2;
        const uint32_t bB = sb + 2 * PIECE_ELEMS * 2;

        #pragma unroll
        for (int ks = 0; ks < 2; ks++) {
            const int kb = ks * 16 + colsel;

            uint32_t bh[2][4];
            #pragma unroll
            for (int p = 0; p < 2; p++) {
                uint32_t off = (uint32_t)(((wn * 32 + p * 16 + rowsel) * RSTRIDE + kb) * 2);
                ldm_x4(bh[p][0], bh[p][1], bh[p][2], bh[p][3], bB + off);
            }

            #pragma unroll
            for (int mt = 0; mt < 4; mt++) {
                uint32_t off = (uint32_t)(((wm * 64 + mt * 16 + rowsel) * RSTRIDE + kb) * 2);
                uint32_t ah[4], al[4];
                ldm_x4(ah[0], ah[1], ah[2], ah[3], aH + off);
                ldm_x4(al[0], al[1], al[2], al[3], aL + off);

                #pragma unroll
                for (int nt = 0; nt < 4; nt++) {
                    const int p = nt >> 1, o = nt & 1;
                    mma16816(acc[mt][nt], ah, bh[p][0 + o], bh[p][2 + o]);
                }
                #pragma unroll
                for (int nt = 0; nt < 4; nt++) {
                    const int p = nt >> 1, o = nt & 1;
                    mma16816(acc[mt][nt], al, bh[p][0 + o], bh[p][2 + o]);
                }
            }
        }
        __syncthreads();
        if (kc + 2 < NKC) load_stage(s, (kc + 2) * GBK);
        CP_COMMIT();
    }

    const int r   = lane >> 2;
    const int cp2 = (lane & 3) * 2;

    if (MODE == 0) {
        // ---- transposed epilogue: u tile -> g_ut[b, d, t] via smem ----
        CP_WAIT0();
        __syncthreads();
        float* tsm = reinterpret_cast<float*>(smem);   // 64 cols x 132 stride
        const int bb = m0 / SEQ;
        const int t0 = m0 % SEQ;
        #pragma unroll
        for (int round = 0; round < 2; round++) {
            if ((wn >> 1) == round) {
                const int colb = (wn & 1) * 32;
                #pragma unroll
                for (int mt = 0; mt < 4; mt++)
                    #pragma unroll
                    for (int nt = 0; nt < 4; nt++)
                        #pragma unroll
                        for (int h = 0; h < 2; h++) {
                            const int row = wm * 64 + mt * 16 + r + h * 8;
                            const int col = colb + nt * 8 + cp2;
                            tsm[col * 132 + row]       = acc[mt][nt][2 * h + 0];
                            tsm[(col + 1) * 132 + row] = acc[mt][nt][2 * h + 1];
                        }
            }
            __syncthreads();
            const int d0r = n0 + round * 64;
            #pragma unroll
            for (int i = 0; i < 8; i++) {
                const int idx = tid + i * 256;
                const int c   = idx >> 5;
                const int tq  = idx & 31;
                float4 v = *(float4*)&tsm[c * 132 + tq * 4];
                *(float4*)&g_ut[(size_t)(bb * DM + d0r + c) * SEQ + t0 + tq * 4] = v;
            }
            __syncthreads();
        }
        return;
    }

    #pragma unroll
    for (int mt = 0; mt < 4; mt++) {
        #pragma unroll
        for (int nt = 0; nt < 4; nt++) {
            const int col  = n0 + wn * 32 + nt * 8 + cp2;
            const int row0 = m0 + wm * 64 + mt * 16 + r;
            #pragma unroll
            for (int h = 0; h < 2; h++) {
                const int row = row0 + h * 8;
                const size_t off = (size_t)row * DM + col;
                float v0 = acc[mt][nt][2 * h + 0];
                float v1 = acc[mt][nt][2 * h + 1];
                if (MODE == 1) {
                    v0 = 1.f / (1.f + __expf(-(v0 + bias[col + 0])));
                    v1 = 1.f / (1.f + __expf(-(v1 + bias[col + 1])));
                } else {
                    float2 xv = *(const float2*)&xres[off];
                    float2 gv = *(const float2*)&gate[off];
                    v0 = xv.x + gv.x * v0;
                    v1 = xv.y + gv.y * v1;
                }
                *(float2*)&C[off] = make_float2(v0, v1);
            }
        }
    }
}

// ---------------- S4D scan body (packed f32x2, coalesced I/O) --------------
// One warp per (b, d); called with per-warp smem region.
__device__ __forceinline__ void scan_body(int b, int d,
                                          unsigned long long* spw,
                                          const float* __restrict__ D_p)
{
    const int lane = threadIdx.x & 31;
    const int base = d * SN;
    const unsigned long long ar2  = pk2(g_ar[base + lane],  g_ar[base + 32 + lane]);
    const unsigned long long ai2  = pk2(g_ai[base + lane],  g_ai[base + 32 + lane]);
    const unsigned long long nai2 = pk2(-g_ai[base + lane], -g_ai[base + 32 + lane]);
    const unsigned long long cb2  = pk2(g_cb[base + lane],  g_cb[base + 32 + lane]);
    const float Dp  = D_p[d];

    const float* up = g_ut + (size_t)(b * DM + d) * SEQ;
    __half* yh = g_yht + (size_t)(b * DM + d) * SEQ;
    __half* yl = g_ylt + (size_t)(b * DM + d) * SEQ;

    unsigned long long gr2 = 0ull, gi2 = 0ull;
    float ucur = up[lane];

    const int NT = SEQ / 32;
    for (int tt = 0; tt < NT; tt++) {
        float unext = 0.f;
        if (tt + 1 < NT) unext = up[(tt + 1) * 32 + lane];

        #pragma unroll
        for (int j = 0; j < 32; j++) {
            float uj = __shfl_sync(0xffffffffu, ucur, j);
            unsigned long long u2  = pk2(uj, uj);
            unsigned long long nr  = fma2(ar2, gr2, fma2(nai2, gi2, mul2(cb2, u2)));
            unsigned long long ni  = fma2(ai2, gr2, mul2(ar2, gi2));
            gr2 = nr; gi2 = ni;
            spw[j * 33 + lane] = nr;
        }
        __syncwarp();

        unsigned long long accA = spw[lane * 33 + 0];
        unsigned long long accB = spw[lane * 33 + 1];
        #pragma unroll
        for (int k2 = 2; k2 < 32; k2 += 2) {
            accA = add2(accA, spw[lane * 33 + k2]);
            accB = add2(accB, spw[lane * 33 + k2 + 1]);
        }
        accA = add2(accA, accB);
        float s0, s1;
        upk2(accA, s0, s1);
        float acc = fmaf(Dp, ucur, s0 + s1);

        const int oidx = tt * 32 + lane;
        __half h = __float2half(acc);
        yh[oidx] = h;
        yl[oidx] = __float2half(acc - __half2float(h));
        __syncwarp();

        ucur = unext;
    }
}

// ---------------- kernels --------------------------------------------------
__global__ __launch_bounds__(256, 2) void gemm_u_kernel(
    const __half* __restrict__ Ah, const __half* __restrict__ Al,
    const __half* __restrict__ B)
{
    extern __shared__ char dsm[];
    gemm_body<0>(blockIdx.x, blockIdx.y, dsm, Ah, Al, B,
                 nullptr, nullptr, nullptr, nullptr);
}

__global__ __launch_bounds__(256, 2) void gemm_out_kernel(
    const __half* __restrict__ Ah, const __half* __restrict__ Al,
    const __half* __restrict__ B, float* __restrict__ C,
    const float* __restrict__ xres, const float* __restrict__ gate)
{
    extern __shared__ char dsm[];
    gemm_body<2>(blockIdx.x, blockIdx.y, dsm, Ah, Al, B,
                 C, nullptr, xres, gate);
}

// Heterogeneous launch: blocks [0,256) = gate GEMM tiles (tensor-bound),
// blocks [256,512) = scan blocks (FMA/issue-bound). Co-resident on each SM
// they fill complementary pipes.
#define GATE_BLOCKS 256
__global__ __launch_bounds__(256, 2) void gate_scan_kernel(
    const __half* __restrict__ xh, const __half* __restrict__ xl,
    const __half* __restrict__ wg, float* __restrict__ pg,
    const float* __restrict__ bias, const float* __restrict__ D_p)
{
    extern __shared__ char dsm[];
    if (blockIdx.x < GATE_BLOCKS) {
        gemm_body<1>(blockIdx.x & 3, blockIdx.x >> 2, dsm, xh, xl, wg,
                     pg, bias, nullptr, nullptr);
    } else {
        const int sidx = blockIdx.x - GATE_BLOCKS;   // 0..255
        const int b  = sidx >> 6;                    // 0..3
        const int d  = (sidx & 63) * 8 + (threadIdx.x >> 5);
        unsigned long long* spw =
            reinterpret_cast<unsigned long long*>(dsm) + (threadIdx.x >> 5) * (32 * 33);
        scan_body(b, d, spw, D_p);
    }
}

// ---------------- launch --------------------------------------------------
extern "C" void kernel_launch(void* const* d_in, const int* in_sizes, int n_in,
                              void* d_out, int out_size)
{
    const float* x          = (const float*)d_in[0];
    const float* log_A_real = (const float*)d_in[1];
    const float* A_imag     = (const float*)d_in[2];
    const float* B_p        = (const float*)d_in[3];
    const float* C_p        = (const float*)d_in[4];
    const float* D_p        = (const float*)d_in[5];
    const float* log_dt     = (const float*)d_in[6];
    const float* W_in       = (const float*)d_in[7];
    const float* W_out      = (const float*)d_in[8];
    const float* W_gate     = (const float*)d_in[9];
    const float* b_gate     = (const float*)d_in[10];
    float* out = (float*)d_out;

    float *pg;
    __half *xh, *xl, *yh, *yl, *wi, *wg, *wo;
    cudaGetSymbolAddress((void**)&pg, g_gate);
    cudaGetSymbolAddress((void**)&xh, g_xh);
    cudaGetSymbolAddress((void**)&xl, g_xl);
    cudaGetSymbolAddress((void**)&yh, g_yh);
    cudaGetSymbolAddress((void**)&yl, g_yl);
    cudaGetSymbolAddress((void**)&wi, g_wi);
    cudaGetSymbolAddress((void**)&wg, g_wg);
    cudaGetSymbolAddress((void**)&wo, g_wo);

    cudaFuncSetAttribute(gemm_u_kernel,
                         cudaFuncAttributeMaxDynamicSharedMemorySize, GEMM_SMEM);
    cudaFuncSetAttribute(gemm_out_kernel,
                         cudaFuncAttributeMaxDynamicSharedMemorySize, GEMM_SMEM);
    cudaFuncSetAttribute(gate_scan_kernel,
                         cudaFuncAttributeMaxDynamicSharedMemorySize, FUSED_SMEM);

    param_kernel<<<(DM * SN + 255) / 256, 256>>>(log_A_real, A_imag, B_p, C_p, log_dt);

    split_kernel<<<(M_TOT * DM + 255) / 256, 256>>>(x, xh, xl, M_TOT * DM);
    wcvt_kernel<<<(3 * DM * DM + 255) / 256, 256>>>(W_in, W_gate, W_out, wi, wg, wo);

    // u projection (writes g_ut transposed)
    gemm_u_kernel<<<dim3(4, M_TOT / GBM), 256, GEMM_SMEM>>>(xh, xl, wi);

    // gate GEMM + scan, co-resident in one launch
    gate_scan_kernel<<<512, 256, FUSED_SMEM>>>(xh, xl, wg, pg, b_gate, D_p);

    transpose_y_kernel<<<dim3(DM / 32, SEQ / 32, NBATCH), dim3(32, 8)>>>();

    gemm_out_kernel<<<dim3(4, M_TOT / GBM), 256, GEMM_SMEM>>>(yh, yl, wo, out, x, pg);
}